// round 8
// baseline (speedup 1.0000x reference)
#include <cuda_runtime.h>
#include <cstdint>
#include <math.h>

#define LL 512
#define CC 128
#define NROWS (LL*LL)   // 262144

// ---- scratch ----
__device__ float g_X[NROWS*CC];     // normalized input (n-major)
__device__ float g_Lt[CC*NROWS];    // left  gated+masked, c-major planes, k-interleaved [0,4,1,5,2,6,3,7] per 8-group
__device__ float g_Rt[CC*NROWS];    // right gated+masked, same layout
__device__ float g_Fg[NROWS*CC];    // sigmoid(final gate), n-major
__device__ float g_Ot[CC*NROWS];    // einsum output, c-major planes [c][i*512+j]

__device__ __forceinline__ float sigf(float x) {
    return 1.0f / (1.0f + __expf(-x));
}
__device__ __forceinline__ float tf32r(float x) {
    uint32_t y;
    asm("cvt.rna.tf32.f32 %0, %1;" : "=r"(y) : "f"(x));
    return __uint_as_float(y);
}
__device__ __forceinline__ void mma_tf32(float* c, const uint32_t* a, const uint32_t* b) {
    asm volatile(
        "mma.sync.aligned.m16n8k8.row.col.f32.tf32.tf32.f32 "
        "{%0,%1,%2,%3}, {%4,%5,%6,%7}, {%8,%9}, {%0,%1,%2,%3};"
        : "+f"(c[0]), "+f"(c[1]), "+f"(c[2]), "+f"(c[3])
        : "r"(a[0]), "r"(a[1]), "r"(a[2]), "r"(a[3]), "r"(b[0]), "r"(b[1]));
}

// ---------------- LayerNorm: one warp per row of 128 ----------------
__global__ void ln_kernel(const float* __restrict__ in,
                          const float* __restrict__ scale,
                          const float* __restrict__ bias,
                          float* __restrict__ out)
{
    int warp = (blockIdx.x * blockDim.x + threadIdx.x) >> 5;
    int lane = threadIdx.x & 31;
    if (warp >= NROWS) return;
    const float4 v = *(const float4*)(in + (size_t)warp * CC + lane * 4);
    float s  = v.x + v.y + v.z + v.w;
    float sq = v.x*v.x + v.y*v.y + v.z*v.z + v.w*v.w;
    #pragma unroll
    for (int o = 16; o > 0; o >>= 1) {
        s  += __shfl_xor_sync(0xffffffffu, s,  o);
        sq += __shfl_xor_sync(0xffffffffu, sq, o);
    }
    float mean = s * (1.0f / CC);
    float var  = sq * (1.0f / CC) - mean * mean;
    float rstd = rsqrtf(var + 1e-5f);
    float4 sc = *(const float4*)(scale + lane * 4);
    float4 bi = *(const float4*)(bias  + lane * 4);
    float4 r;
    r.x = (v.x - mean) * rstd * sc.x + bi.x;
    r.y = (v.y - mean) * rstd * sc.y + bi.y;
    r.z = (v.z - mean) * rstd * sc.z + bi.z;
    r.w = (v.w - mean) * rstd * sc.w + bi.w;
    *(float4*)(out + (size_t)warp * CC + lane * 4) = r;
}

// ---------------- single-weight tf32 GEMM (Fg): out = sigmoid(X@W + b) ----------------
__global__ void __launch_bounds__(256) gemm_mma_s(
    const float* __restrict__ X,
    const float* __restrict__ W,
    const float* __restrict__ B,
    float* __restrict__ out)
{
    __shared__ __align__(16) float Xs[128 * 20];
    __shared__ __align__(16) float Ws[16 * 136];
    const int r0   = blockIdx.x * 128;
    const int tid  = threadIdx.x;
    const int wid  = tid >> 5;
    const int lane = tid & 31;
    const int warp_m = wid >> 2;
    const int warp_n = wid & 3;
    const int lr = lane >> 2;
    const int lc = lane & 3;

    float acc[16][4];
    #pragma unroll
    for (int t = 0; t < 16; t++)
        #pragma unroll
        for (int q = 0; q < 4; q++) acc[t][q] = 0.0f;

    for (int k0 = 0; k0 < CC; k0 += 16) {
        #pragma unroll
        for (int u = 0; u < 2; u++) {
            int idx = tid + u * 256;
            int r = idx >> 2;
            int q = idx & 3;
            float4 v = *(const float4*)(X + (size_t)(r0 + r) * CC + k0 + q * 4);
            v.x = tf32r(v.x); v.y = tf32r(v.y); v.z = tf32r(v.z); v.w = tf32r(v.w);
            *(float4*)(&Xs[r * 20 + q * 4]) = v;
        }
        #pragma unroll
        for (int u = 0; u < 2; u++) {
            int idx = tid + u * 256;
            int k = idx >> 5;
            int q = idx & 31;
            float4 v = *(const float4*)(W + (size_t)(k0 + k) * CC + q * 4);
            v.x = tf32r(v.x); v.y = tf32r(v.y); v.z = tf32r(v.z); v.w = tf32r(v.w);
            *(float4*)(&Ws[k * 136 + q * 4]) = v;
        }
        __syncthreads();
        #pragma unroll
        for (int ks = 0; ks < 16; ks += 8) {
            uint32_t a[4][4], b[4][2];
            #pragma unroll
            for (int mt = 0; mt < 4; mt++) {
                int rb = (warp_m * 64 + mt * 16 + lr) * 20 + ks + lc;
                a[mt][0] = __float_as_uint(Xs[rb]);
                a[mt][1] = __float_as_uint(Xs[rb + 8 * 20]);
                a[mt][2] = __float_as_uint(Xs[rb + 4]);
                a[mt][3] = __float_as_uint(Xs[rb + 8 * 20 + 4]);
            }
            #pragma unroll
            for (int nt = 0; nt < 4; nt++) {
                int nb = warp_n * 32 + nt * 8 + lr;
                b[nt][0] = __float_as_uint(Ws[(ks + lc) * 136 + nb]);
                b[nt][1] = __float_as_uint(Ws[(ks + 4 + lc) * 136 + nb]);
            }
            #pragma unroll
            for (int mt = 0; mt < 4; mt++)
                #pragma unroll
                for (int nt = 0; nt < 4; nt++)
                    mma_tf32(acc[mt * 4 + nt], a[mt], b[nt]);
        }
        __syncthreads();
    }

    #pragma unroll
    for (int mt = 0; mt < 4; mt++) {
        #pragma unroll
        for (int nt = 0; nt < 4; nt++) {
            int col = warp_n * 32 + nt * 8 + lc * 2;
            float2 bb = *(const float2*)(B + col);
            #pragma unroll
            for (int h = 0; h < 2; h++) {
                int row = r0 + warp_m * 64 + mt * 16 + lr + h * 8;
                float2 v;
                v.x = sigf(acc[mt * 4 + nt][h * 2 + 0] + bb.x);
                v.y = sigf(acc[mt * 4 + nt][h * 2 + 1] + bb.y);
                *(float2*)(out + (size_t)row * CC + col) = v;
            }
        }
    }
}

// ---------------- fused projection + gate + mask + c-major transpose (k-interleaved) ----------------
__global__ void __launch_bounds__(256) proj_lr(
    const float* __restrict__ X,
    const float* __restrict__ w_l,  const float* __restrict__ w_lg,
    const float* __restrict__ b_l,  const float* __restrict__ b_lg,
    const float* __restrict__ w_r,  const float* __restrict__ w_rg,
    const float* __restrict__ b_r,  const float* __restrict__ b_rg,
    const float* __restrict__ mask)
{
    __shared__ __align__(16) float sbuf[128 * 68];
    float* Xs  = sbuf;                 // 128*20
    float* Ws  = sbuf + 2560;          // 16*72
    float* Wgs = sbuf + 2560 + 1152;   // 16*72

    const int sel  = blockIdx.y >> 1;
    const int half = blockIdx.y & 1;
    const float* W  = (sel ? w_r  : w_l)  + half * 64;
    const float* Wg = (sel ? w_rg : w_lg) + half * 64;
    const float* B  = (sel ? b_r  : b_l)  + half * 64;
    const float* Bg = (sel ? b_rg : b_lg) + half * 64;
    float* dstT = (sel ? g_Rt : g_Lt) + (size_t)(half * 64) * NROWS;

    const int n0   = blockIdx.x * 128;
    const int tid  = threadIdx.x;
    const int wid  = tid >> 5;
    const int lane = tid & 31;
    const int warp_m = wid >> 2;
    const int warp_n = wid & 3;
    const int lr = lane >> 2;
    const int lc = lane & 3;

    float acc[8][4], accg[8][4];
    #pragma unroll
    for (int t = 0; t < 8; t++)
        #pragma unroll
        for (int q = 0; q < 4; q++) { acc[t][q] = 0.0f; accg[t][q] = 0.0f; }

    for (int k0 = 0; k0 < CC; k0 += 16) {
        #pragma unroll
        for (int u = 0; u < 2; u++) {
            int idx = tid + u * 256;
            int r = idx >> 2;
            int q = idx & 3;
            float4 v = *(const float4*)(X + (size_t)(n0 + r) * CC + k0 + q * 4);
            v.x = tf32r(v.x); v.y = tf32r(v.y); v.z = tf32r(v.z); v.w = tf32r(v.w);
            *(float4*)(&Xs[r * 20 + q * 4]) = v;
        }
        {
            int k = tid >> 4;
            int q = tid & 15;
            float4 v = *(const float4*)(W + (size_t)(k0 + k) * CC + q * 4);
            v.x = tf32r(v.x); v.y = tf32r(v.y); v.z = tf32r(v.z); v.w = tf32r(v.w);
            *(float4*)(&Ws[k * 72 + q * 4]) = v;
            float4 g = *(const float4*)(Wg + (size_t)(k0 + k) * CC + q * 4);
            g.x = tf32r(g.x); g.y = tf32r(g.y); g.z = tf32r(g.z); g.w = tf32r(g.w);
            *(float4*)(&Wgs[k * 72 + q * 4]) = g;
        }
        __syncthreads();
        #pragma unroll
        for (int ks = 0; ks < 16; ks += 8) {
            uint32_t a[4][4], b[2][2], bg[2][2];
            #pragma unroll
            for (int mt = 0; mt < 4; mt++) {
                int rb = (warp_m * 64 + mt * 16 + lr) * 20 + ks + lc;
                a[mt][0] = __float_as_uint(Xs[rb]);
                a[mt][1] = __float_as_uint(Xs[rb + 8 * 20]);
                a[mt][2] = __float_as_uint(Xs[rb + 4]);
                a[mt][3] = __float_as_uint(Xs[rb + 8 * 20 + 4]);
            }
            #pragma unroll
            for (int nt = 0; nt < 2; nt++) {
                int nb = warp_n * 16 + nt * 8 + lr;
                b[nt][0]  = __float_as_uint(Ws[(ks + lc) * 72 + nb]);
                b[nt][1]  = __float_as_uint(Ws[(ks + 4 + lc) * 72 + nb]);
                bg[nt][0] = __float_as_uint(Wgs[(ks + lc) * 72 + nb]);
                bg[nt][1] = __float_as_uint(Wgs[(ks + 4 + lc) * 72 + nb]);
            }
            #pragma unroll
            for (int mt = 0; mt < 4; mt++)
                #pragma unroll
                for (int nt = 0; nt < 2; nt++) {
                    mma_tf32(acc[mt * 2 + nt], a[mt], b[nt]);
                    mma_tf32(accg[mt * 2 + nt], a[mt], bg[nt]);
                }
        }
        __syncthreads();
    }

    // epilogue: gate+mask into 128x64 smem tile, then transposed c-major write (k-interleaved)
    float (*tile)[68] = (float (*)[68])sbuf;
    #pragma unroll
    for (int mt = 0; mt < 4; mt++) {
        #pragma unroll
        for (int nt = 0; nt < 2; nt++) {
            int col = warp_n * 16 + nt * 8 + lc * 2;
            float2 bb  = *(const float2*)(B + col);
            float2 bbg = *(const float2*)(Bg + col);
            #pragma unroll
            for (int h = 0; h < 2; h++) {
                int rl = warp_m * 64 + mt * 16 + lr + h * 8;
                int n = n0 + rl;
                float pm = mask[n >> 9] * mask[n & 511];
                float vx = (acc[mt * 2 + nt][h * 2 + 0] + bb.x) * pm
                         * sigf(accg[mt * 2 + nt][h * 2 + 0] + bbg.x);
                float vy = (acc[mt * 2 + nt][h * 2 + 1] + bb.y) * pm
                         * sigf(accg[mt * 2 + nt][h * 2 + 1] + bbg.y);
                tile[rl][col]     = tf32r(vx);
                tile[rl][col + 1] = tf32r(vy);
            }
        }
    }
    __syncthreads();
    {
        // interleave order within each 8-k group: position m <- orig O8[m]
        const int O8[8] = {0, 4, 1, 5, 2, 6, 3, 7};
        int c = tid >> 2;
        int h = tid & 3;
        float* dst = dstT + (size_t)c * NROWS + n0 + h * 32;
        #pragma unroll
        for (int q = 0; q < 8; q++) {
            int g8 = (q >> 1) * 8;
            int e  = (q & 1) * 4;
            float4 v;
            v.x = tile[h * 32 + g8 + O8[e + 0]][c];
            v.y = tile[h * 32 + g8 + O8[e + 1]][c];
            v.z = tile[h * 32 + g8 + O8[e + 2]][c];
            v.w = tile[h * 32 + g8 + O8[e + 3]][c];
            *(float4*)(dst + q * 4) = v;
        }
    }
}

// ---------------- einsum via mma.sync tf32 on k-interleaved operands ----------------
// Block 128i x 128j, 4 warps (2x2), warp tile 64x64, k-chunk 16, smem stride 24.
// Fragments load as LDS.64 pairs (orig k lc, lc+4) at interleaved position ks+2*lc.
__global__ void __launch_bounds__(128) einsum_mma()
{
    __shared__ __align__(16) float As[128 * 24];
    __shared__ __align__(16) float Bs[128 * 24];
    const int c  = blockIdx.z;
    const int i0 = blockIdx.x * 128;
    const int j0 = blockIdx.y * 128;
    const int tid  = threadIdx.x;
    const int wid  = tid >> 5;
    const int lane = tid & 31;
    const int warp_m = wid >> 1;
    const int warp_n = wid & 1;
    const int lr = lane >> 2;
    const int lc = lane & 3;

    const float* Ap = g_Lt + (size_t)c * NROWS + (size_t)i0 * 512;
    const float* Bp = g_Rt + (size_t)c * NROWS + (size_t)j0 * 512;

    float acc[32][4];
    #pragma unroll
    for (int t = 0; t < 32; t++)
        #pragma unroll
        for (int q = 0; q < 4; q++) acc[t][q] = 0.0f;

    for (int k0 = 0; k0 < LL; k0 += 16) {
        #pragma unroll
        for (int u = 0; u < 4; u++) {
            int idx = tid + u * 128;       // 0..511
            int r = idx >> 2;
            int q = idx & 3;
            *(float4*)(&As[r * 24 + q * 4]) = *(const float4*)(Ap + (size_t)r * 512 + k0 + q * 4);
            *(float4*)(&Bs[r * 24 + q * 4]) = *(const float4*)(Bp + (size_t)r * 512 + k0 + q * 4);
        }
        __syncthreads();
        #pragma unroll
        for (int ks = 0; ks < 16; ks += 8) {
            uint32_t a[4][4], b[8][2];
            #pragma unroll
            for (int mt = 0; mt < 4; mt++) {
                int rb = (warp_m * 64 + mt * 16 + lr) * 24 + ks + 2 * lc;
                float2 p0 = *(const float2*)(&As[rb]);
                float2 p1 = *(const float2*)(&As[rb + 8 * 24]);
                a[mt][0] = __float_as_uint(p0.x);
                a[mt][1] = __float_as_uint(p1.x);
                a[mt][2] = __float_as_uint(p0.y);
                a[mt][3] = __float_as_uint(p1.y);
            }
            #pragma unroll
            for (int nt = 0; nt < 8; nt++) {
                int rb = (warp_n * 64 + nt * 8 + lr) * 24 + ks + 2 * lc;
                float2 pb = *(const float2*)(&Bs[rb]);
                b[nt][0] = __float_as_uint(pb.x);
                b[nt][1] = __float_as_uint(pb.y);
            }
            #pragma unroll
            for (int mt = 0; mt < 4; mt++)
                #pragma unroll
                for (int nt = 0; nt < 8; nt++)
                    mma_tf32(acc[mt * 8 + nt], a[mt], b[nt]);
        }
        __syncthreads();
    }

    float* Op = g_Ot + (size_t)c * NROWS;
    #pragma unroll
    for (int mt = 0; mt < 4; mt++) {
        #pragma unroll
        for (int nt = 0; nt < 8; nt++) {
            int col = j0 + warp_n * 64 + nt * 8 + lc * 2;
            #pragma unroll
            for (int h = 0; h < 2; h++) {
                int row = i0 + warp_m * 64 + mt * 16 + lr + h * 8;
                float2 v;
                v.x = acc[mt * 8 + nt][h * 2 + 0];
                v.y = acc[mt * 8 + nt][h * 2 + 1];
                *(float2*)(Op + (size_t)row * 512 + col) = v;
            }
        }
    }
}

// ---------------- fused: load Ot tile (c-major) + LayerNorm + GEMM(w_out) + gate ----------------
// Block: 128 n-rows x 128 cols, 256 threads. Dynamic smem.
__global__ void __launch_bounds__(256) gemm_out_fused(
    const float* __restrict__ W,
    const float* __restrict__ B,
    const float* __restrict__ fsc,
    const float* __restrict__ fbi,
    const float* __restrict__ gate,
    float* __restrict__ out)
{
    extern __shared__ float dsm[];
    float* tileA = dsm;                    // 128 c x 129 (holds Ot tile, c-major)
    float* Xs    = dsm + 128 * 129;        // 128 x 20
    float* Ws    = Xs + 128 * 20;          // 16 x 136
    float* s_mu  = Ws + 16 * 136;          // 128
    float* s_rs  = s_mu + 128;             // 128

    const int n0   = blockIdx.x * 128;
    const int tid  = threadIdx.x;
    const int wid  = tid >> 5;
    const int lane = tid & 31;
    const int warp_m = wid >> 2;
    const int warp_n = wid & 3;
    const int lr = lane >> 2;
    const int lc = lane & 3;

    // load Ot tile: 128 c x 128 n  (float4 gmem load, scalar smem stores: stride 129 is not
    // 16B-aligned for odd rows -- vector smem stores would fault)
    #pragma unroll
    for (int u = 0; u < 16; u++) {
        int idx = tid + u * 256;      // 0..4095 = 128c x 32 float4
        int cc = idx >> 5;
        int q  = idx & 31;
        float4 v = *(const float4*)(g_Ot + (size_t)cc * NROWS + n0 + q * 4);
        float* trow = &tileA[cc * 129 + q * 4];
        trow[0] = v.x; trow[1] = v.y; trow[2] = v.z; trow[3] = v.w;
    }
    __syncthreads();

    // LN stats: warp w handles rows w*16 .. w*16+15
    #pragma unroll
    for (int rr = 0; rr < 16; rr++) {
        int r = wid * 16 + rr;
        float s = 0.0f, sq = 0.0f;
        #pragma unroll
        for (int m = 0; m < 4; m++) {
            float v = tileA[(lane + m * 32) * 129 + r];
            s += v; sq += v * v;
        }
        #pragma unroll
        for (int o = 16; o > 0; o >>= 1) {
            s  += __shfl_xor_sync(0xffffffffu, s,  o);
            sq += __shfl_xor_sync(0xffffffffu, sq, o);
        }
        if (lane == 0) {
            float mean = s * (1.0f / CC);
            s_mu[r] = mean;
            s_rs[r] = rsqrtf(sq * (1.0f / CC) - mean * mean + 1e-5f);
        }
    }
    __syncthreads();

    float acc[16][4];
    #pragma unroll
    for (int t = 0; t < 16; t++)
        #pragma unroll
        for (int q = 0; q < 4; q++) acc[t][q] = 0.0f;

    for (int k0 = 0; k0 < CC; k0 += 16) {
        // build normalized tf32 A-chunk from tileA
        #pragma unroll
        for (int u = 0; u < 8; u++) {
            int idx = tid + u * 256;      // 0..2047
            int kk = idx & 15;
            int r  = idx >> 4;
            float v = (tileA[(k0 + kk) * 129 + r] - s_mu[r]) * s_rs[r]
                      * fsc[k0 + kk] + fbi[k0 + kk];
            Xs[r * 20 + kk] = tf32r(v);
        }
        #pragma unroll
        for (int u = 0; u < 2; u++) {
            int idx = tid + u * 256;
            int k = idx >> 5;
            int q = idx & 31;
            float4 v = *(const float4*)(W + (size_t)(k0 + k) * CC + q * 4);
            v.x = tf32r(v.x); v.y = tf32r(v.y); v.z = tf32r(v.z); v.w = tf32r(v.w);
            *(float4*)(&Ws[k * 136 + q * 4]) = v;
        }
        __syncthreads();
        #pragma unroll
        for (int ks = 0; ks < 16; ks += 8) {
            uint32_t a[4][4], b[4][2];
            #pragma unroll
            for (int mt = 0; mt < 4; mt++) {
                int rb = (warp_m * 64 + mt * 16 + lr) * 20 + ks + lc;
                a[mt][0] = __float_as_uint(Xs[rb]);
                a[mt][1] = __float_as_uint(Xs[rb + 8 * 20]);
                a[mt][2] = __float_as_uint(Xs[rb + 4]);
                a[mt][3] = __float_as_uint(Xs[rb + 8 * 20 + 4]);
            }
            #pragma unroll
            for (int nt = 0; nt < 4; nt++) {
                int nb = warp_n * 32 + nt * 8 + lr;
                b[nt][0] = __float_as_uint(Ws[(ks + lc) * 136 + nb]);
                b[nt][1] = __float_as_uint(Ws[(ks + 4 + lc) * 136 + nb]);
            }
            #pragma unroll
            for (int mt = 0; mt < 4; mt++)
                #pragma unroll
                for (int nt = 0; nt < 4; nt++)
                    mma_tf32(acc[mt * 4 + nt], a[mt], b[nt]);
        }
        __syncthreads();
    }

    #pragma unroll
    for (int mt = 0; mt < 4; mt++) {
        #pragma unroll
        for (int nt = 0; nt < 4; nt++) {
            int col = warp_n * 32 + nt * 8 + lc * 2;
            float2 bb = *(const float2*)(B + col);
            #pragma unroll
            for (int h = 0; h < 2; h++) {
                int row = n0 + warp_m * 64 + mt * 16 + lr + h * 8;
                float2 gv = *(const float2*)(gate + (size_t)row * CC + col);
                float2 v;
                v.x = (acc[mt * 4 + nt][h * 2 + 0] + bb.x) * gv.x;
                v.y = (acc[mt * 4 + nt][h * 2 + 1] + bb.y) * gv.y;
                *(float2*)(out + (size_t)row * CC + col) = v;
            }
        }
    }
}

// ---------------- host launch ----------------
extern "C" void kernel_launch(void* const* d_in, const int* in_sizes, int n_in,
                              void* d_out, int out_size)
{
    const float* act         = (const float*)d_in[0];
    const float* mask        = (const float*)d_in[1];
    const float* norm_scale  = (const float*)d_in[2];
    const float* norm_bias   = (const float*)d_in[3];
    const float* w_left      = (const float*)d_in[4];
    const float* b_left      = (const float*)d_in[5];
    const float* w_right     = (const float*)d_in[6];
    const float* b_right     = (const float*)d_in[7];
    const float* w_lgate     = (const float*)d_in[8];
    const float* b_lgate     = (const float*)d_in[9];
    const float* w_rgate     = (const float*)d_in[10];
    const float* b_rgate     = (const float*)d_in[11];
    const float* fnorm_scale = (const float*)d_in[12];
    const float* fnorm_bias  = (const float*)d_in[13];
    const float* w_out       = (const float*)d_in[14];
    const float* b_out       = (const float*)d_in[15];
    const float* w_fgate     = (const float*)d_in[16];
    const float* b_fgate     = (const float*)d_in[17];

    float *X, *Fg;
    cudaGetSymbolAddress((void**)&X,  g_X);
    cudaGetSymbolAddress((void**)&Fg, g_Fg);

    // dynamic smem for the fused output GEMM
    const int out_smem = (128 * 129 + 128 * 20 + 16 * 136 + 256) * sizeof(float);
    static int attr_set = 0;
    if (!attr_set) {
        cudaFuncSetAttribute(gemm_out_fused,
                             cudaFuncAttributeMaxDynamicSharedMemorySize, out_smem);
        attr_set = 1;
    }

    // 1) x = LN(act)
    ln_kernel<<<NROWS / 8, 256>>>(act, norm_scale, norm_bias, X);

    // 2) fused projections + gates + mask -> Lt, Rt (c-major, k-interleaved)
    proj_lr<<<dim3(NROWS / 128, 4), 256>>>(
        X, w_left, w_lgate, b_left, b_lgate,
        w_right, w_rgate, b_right, b_rgate, mask);

    // 3) final-gate projection: Fg = sigmoid(X @ w_fgate + b_fgate)
    gemm_mma_s<<<NROWS / 128, 256>>>(X, w_fgate, b_fgate, Fg);

    // 4) einsum on tensor cores -> Ot (c-major)
    einsum_mma<<<dim3(4, 4, CC), 128>>>();

    // 5+6) fused: LN(Ot) transpose + output projection + final gate
    gemm_out_fused<<<NROWS / 128, 256, out_smem>>>(
        w_out, b_out, fnorm_scale, fnorm_bias, Fg, (float*)d_out);
}

// round 9
// speedup vs baseline: 1.1288x; 1.1288x over previous
#include <cuda_runtime.h>
#include <cstdint>
#include <math.h>

#define LL 512
#define CC 128
#define NROWS (LL*LL)   // 262144

// ---- scratch ----
__device__ float g_X[NROWS*CC];     // normalized input (n-major)
__device__ float g_Lt[CC*NROWS];    // left  gated+masked, c-major planes [c][i*512+k], tf32-rounded
__device__ float g_Rt[CC*NROWS];    // right gated+masked, same layout
__device__ float g_Fg[NROWS*CC];    // sigmoid(final gate), n-major
__device__ float g_Ot[CC*NROWS];    // einsum output, c-major planes [c][i*512+j]

__device__ __forceinline__ float sigf(float x) {
    return 1.0f / (1.0f + __expf(-x));
}
__device__ __forceinline__ float tf32r(float x) {
    uint32_t y;
    asm("cvt.rna.tf32.f32 %0, %1;" : "=r"(y) : "f"(x));
    return __uint_as_float(y);
}
__device__ __forceinline__ void mma_tf32(float* c, const uint32_t* a, const uint32_t* b) {
    asm volatile(
        "mma.sync.aligned.m16n8k8.row.col.f32.tf32.tf32.f32 "
        "{%0,%1,%2,%3}, {%4,%5,%6,%7}, {%8,%9}, {%0,%1,%2,%3};"
        : "+f"(c[0]), "+f"(c[1]), "+f"(c[2]), "+f"(c[3])
        : "r"(a[0]), "r"(a[1]), "r"(a[2]), "r"(a[3]), "r"(b[0]), "r"(b[1]));
}
__device__ __forceinline__ void cp16(float* smem, const float* gmem) {
    uint32_t s = (uint32_t)__cvta_generic_to_shared(smem);
    asm volatile("cp.async.ca.shared.global [%0], [%1], 16;" :: "r"(s), "l"(gmem));
}

// ---------------- LayerNorm: one warp per row of 128 ----------------
__global__ void ln_kernel(const float* __restrict__ in,
                          const float* __restrict__ scale,
                          const float* __restrict__ bias,
                          float* __restrict__ out)
{
    int warp = (blockIdx.x * blockDim.x + threadIdx.x) >> 5;
    int lane = threadIdx.x & 31;
    if (warp >= NROWS) return;
    const float4 v = *(const float4*)(in + (size_t)warp * CC + lane * 4);
    float s  = v.x + v.y + v.z + v.w;
    float sq = v.x*v.x + v.y*v.y + v.z*v.z + v.w*v.w;
    #pragma unroll
    for (int o = 16; o > 0; o >>= 1) {
        s  += __shfl_xor_sync(0xffffffffu, s,  o);
        sq += __shfl_xor_sync(0xffffffffu, sq, o);
    }
    float mean = s * (1.0f / CC);
    float var  = sq * (1.0f / CC) - mean * mean;
    float rstd = rsqrtf(var + 1e-5f);
    float4 sc = *(const float4*)(scale + lane * 4);
    float4 bi = *(const float4*)(bias  + lane * 4);
    float4 r;
    r.x = (v.x - mean) * rstd * sc.x + bi.x;
    r.y = (v.y - mean) * rstd * sc.y + bi.y;
    r.z = (v.z - mean) * rstd * sc.z + bi.z;
    r.w = (v.w - mean) * rstd * sc.w + bi.w;
    *(float4*)(out + (size_t)warp * CC + lane * 4) = r;
}

// ---------------- single-weight tf32 GEMM (Fg): out = sigmoid(X@W + b) ----------------
__global__ void __launch_bounds__(256) gemm_mma_s(
    const float* __restrict__ X,
    const float* __restrict__ W,
    const float* __restrict__ B,
    float* __restrict__ out)
{
    __shared__ __align__(16) float Xs[128 * 20];
    __shared__ __align__(16) float Ws[16 * 136];
    const int r0   = blockIdx.x * 128;
    const int tid  = threadIdx.x;
    const int wid  = tid >> 5;
    const int lane = tid & 31;
    const int warp_m = wid >> 2;
    const int warp_n = wid & 3;
    const int lr = lane >> 2;
    const int lc = lane & 3;

    float acc[16][4];
    #pragma unroll
    for (int t = 0; t < 16; t++)
        #pragma unroll
        for (int q = 0; q < 4; q++) acc[t][q] = 0.0f;

    for (int k0 = 0; k0 < CC; k0 += 16) {
        #pragma unroll
        for (int u = 0; u < 2; u++) {
            int idx = tid + u * 256;
            int r = idx >> 2;
            int q = idx & 3;
            float4 v = *(const float4*)(X + (size_t)(r0 + r) * CC + k0 + q * 4);
            v.x = tf32r(v.x); v.y = tf32r(v.y); v.z = tf32r(v.z); v.w = tf32r(v.w);
            *(float4*)(&Xs[r * 20 + q * 4]) = v;
        }
        #pragma unroll
        for (int u = 0; u < 2; u++) {
            int idx = tid + u * 256;
            int k = idx >> 5;
            int q = idx & 31;
            float4 v = *(const float4*)(W + (size_t)(k0 + k) * CC + q * 4);
            v.x = tf32r(v.x); v.y = tf32r(v.y); v.z = tf32r(v.z); v.w = tf32r(v.w);
            *(float4*)(&Ws[k * 136 + q * 4]) = v;
        }
        __syncthreads();
        #pragma unroll
        for (int ks = 0; ks < 16; ks += 8) {
            uint32_t a[4][4], b[4][2];
            #pragma unroll
            for (int mt = 0; mt < 4; mt++) {
                int rb = (warp_m * 64 + mt * 16 + lr) * 20 + ks + lc;
                a[mt][0] = __float_as_uint(Xs[rb]);
                a[mt][1] = __float_as_uint(Xs[rb + 8 * 20]);
                a[mt][2] = __float_as_uint(Xs[rb + 4]);
                a[mt][3] = __float_as_uint(Xs[rb + 8 * 20 + 4]);
            }
            #pragma unroll
            for (int nt = 0; nt < 4; nt++) {
                int nb = warp_n * 32 + nt * 8 + lr;
                b[nt][0] = __float_as_uint(Ws[(ks + lc) * 136 + nb]);
                b[nt][1] = __float_as_uint(Ws[(ks + 4 + lc) * 136 + nb]);
            }
            #pragma unroll
            for (int mt = 0; mt < 4; mt++)
                #pragma unroll
                for (int nt = 0; nt < 4; nt++)
                    mma_tf32(acc[mt * 4 + nt], a[mt], b[nt]);
        }
        __syncthreads();
    }

    #pragma unroll
    for (int mt = 0; mt < 4; mt++) {
        #pragma unroll
        for (int nt = 0; nt < 4; nt++) {
            int col = warp_n * 32 + nt * 8 + lc * 2;
            float2 bb = *(const float2*)(B + col);
            #pragma unroll
            for (int h = 0; h < 2; h++) {
                int row = r0 + warp_m * 64 + mt * 16 + lr + h * 8;
                float2 v;
                v.x = sigf(acc[mt * 4 + nt][h * 2 + 0] + bb.x);
                v.y = sigf(acc[mt * 4 + nt][h * 2 + 1] + bb.y);
                *(float2*)(out + (size_t)row * CC + col) = v;
            }
        }
    }
}

// ---------------- fused projection + gate + mask + c-major transpose ----------------
__global__ void __launch_bounds__(256) proj_lr(
    const float* __restrict__ X,
    const float* __restrict__ w_l,  const float* __restrict__ w_lg,
    const float* __restrict__ b_l,  const float* __restrict__ b_lg,
    const float* __restrict__ w_r,  const float* __restrict__ w_rg,
    const float* __restrict__ b_r,  const float* __restrict__ b_rg,
    const float* __restrict__ mask)
{
    __shared__ __align__(16) float sbuf[128 * 68];
    float* Xs  = sbuf;                 // 128*20
    float* Ws  = sbuf + 2560;          // 16*72
    float* Wgs = sbuf + 2560 + 1152;   // 16*72

    const int sel  = blockIdx.y >> 1;
    const int half = blockIdx.y & 1;
    const float* W  = (sel ? w_r  : w_l)  + half * 64;
    const float* Wg = (sel ? w_rg : w_lg) + half * 64;
    const float* B  = (sel ? b_r  : b_l)  + half * 64;
    const float* Bg = (sel ? b_rg : b_lg) + half * 64;
    float* dstT = (sel ? g_Rt : g_Lt) + (size_t)(half * 64) * NROWS;

    const int n0   = blockIdx.x * 128;
    const int tid  = threadIdx.x;
    const int wid  = tid >> 5;
    const int lane = tid & 31;
    const int warp_m = wid >> 2;
    const int warp_n = wid & 3;
    const int lr = lane >> 2;
    const int lc = lane & 3;

    float acc[8][4], accg[8][4];
    #pragma unroll
    for (int t = 0; t < 8; t++)
        #pragma unroll
        for (int q = 0; q < 4; q++) { acc[t][q] = 0.0f; accg[t][q] = 0.0f; }

    for (int k0 = 0; k0 < CC; k0 += 16) {
        #pragma unroll
        for (int u = 0; u < 2; u++) {
            int idx = tid + u * 256;
            int r = idx >> 2;
            int q = idx & 3;
            float4 v = *(const float4*)(X + (size_t)(n0 + r) * CC + k0 + q * 4);
            v.x = tf32r(v.x); v.y = tf32r(v.y); v.z = tf32r(v.z); v.w = tf32r(v.w);
            *(float4*)(&Xs[r * 20 + q * 4]) = v;
        }
        {
            int k = tid >> 4;
            int q = tid & 15;
            float4 v = *(const float4*)(W + (size_t)(k0 + k) * CC + q * 4);
            v.x = tf32r(v.x); v.y = tf32r(v.y); v.z = tf32r(v.z); v.w = tf32r(v.w);
            *(float4*)(&Ws[k * 72 + q * 4]) = v;
            float4 g = *(const float4*)(Wg + (size_t)(k0 + k) * CC + q * 4);
            g.x = tf32r(g.x); g.y = tf32r(g.y); g.z = tf32r(g.z); g.w = tf32r(g.w);
            *(float4*)(&Wgs[k * 72 + q * 4]) = g;
        }
        __syncthreads();
        #pragma unroll
        for (int ks = 0; ks < 16; ks += 8) {
            uint32_t a[4][4], b[2][2], bg[2][2];
            #pragma unroll
            for (int mt = 0; mt < 4; mt++) {
                int rb = (warp_m * 64 + mt * 16 + lr) * 20 + ks + lc;
                a[mt][0] = __float_as_uint(Xs[rb]);
                a[mt][1] = __float_as_uint(Xs[rb + 8 * 20]);
                a[mt][2] = __float_as_uint(Xs[rb + 4]);
                a[mt][3] = __float_as_uint(Xs[rb + 8 * 20 + 4]);
            }
            #pragma unroll
            for (int nt = 0; nt < 2; nt++) {
                int nb = warp_n * 16 + nt * 8 + lr;
                b[nt][0]  = __float_as_uint(Ws[(ks + lc) * 72 + nb]);
                b[nt][1]  = __float_as_uint(Ws[(ks + 4 + lc) * 72 + nb]);
                bg[nt][0] = __float_as_uint(Wgs[(ks + lc) * 72 + nb]);
                bg[nt][1] = __float_as_uint(Wgs[(ks + 4 + lc) * 72 + nb]);
            }
            #pragma unroll
            for (int mt = 0; mt < 4; mt++)
                #pragma unroll
                for (int nt = 0; nt < 2; nt++) {
                    mma_tf32(acc[mt * 2 + nt], a[mt], b[nt]);
                    mma_tf32(accg[mt * 2 + nt], a[mt], bg[nt]);
                }
        }
        __syncthreads();
    }

    // epilogue: gate+mask into 128x64 smem tile, then transposed c-major write
    float (*tile)[68] = (float (*)[68])sbuf;
    #pragma unroll
    for (int mt = 0; mt < 4; mt++) {
        #pragma unroll
        for (int nt = 0; nt < 2; nt++) {
            int col = warp_n * 16 + nt * 8 + lc * 2;
            float2 bb  = *(const float2*)(B + col);
            float2 bbg = *(const float2*)(Bg + col);
            #pragma unroll
            for (int h = 0; h < 2; h++) {
                int rl = warp_m * 64 + mt * 16 + lr + h * 8;
                int n = n0 + rl;
                float pm = mask[n >> 9] * mask[n & 511];
                float vx = (acc[mt * 2 + nt][h * 2 + 0] + bb.x) * pm
                         * sigf(accg[mt * 2 + nt][h * 2 + 0] + bbg.x);
                float vy = (acc[mt * 2 + nt][h * 2 + 1] + bb.y) * pm
                         * sigf(accg[mt * 2 + nt][h * 2 + 1] + bbg.y);
                tile[rl][col]     = tf32r(vx);
                tile[rl][col + 1] = tf32r(vy);
            }
        }
    }
    __syncthreads();
    {
        int c = tid >> 2;
        int h = tid & 3;
        float* dst = dstT + (size_t)c * NROWS + n0 + h * 32;
        #pragma unroll
        for (int q = 0; q < 8; q++) {
            int nb = h * 32 + q * 4;
            float4 v;
            v.x = tile[nb + 0][c]; v.y = tile[nb + 1][c];
            v.z = tile[nb + 2][c]; v.w = tile[nb + 3][c];
            *(float4*)(dst + q * 4) = v;
        }
    }
}

// ---------------- einsum via mma.sync tf32, cp.async double-buffered ----------------
// Block 128i x 128j, 4 warps (2x2), warp tile 64x64, k-chunk 16, stride-20 smem.
__global__ void __launch_bounds__(128) einsum_mma()
{
    __shared__ __align__(16) float As[2][128 * 20];
    __shared__ __align__(16) float Bs[2][128 * 20];
    const int c  = blockIdx.z;
    const int i0 = blockIdx.x * 128;
    const int j0 = blockIdx.y * 128;
    const int tid  = threadIdx.x;
    const int wid  = tid >> 5;
    const int lane = tid & 31;
    const int warp_m = wid >> 1;
    const int warp_n = wid & 1;
    const int lr = lane >> 2;
    const int lc = lane & 3;

    const float* Ap = g_Lt + (size_t)c * NROWS + (size_t)i0 * 512;
    const float* Bp = g_Rt + (size_t)c * NROWS + (size_t)j0 * 512;

    // per-thread load coordinates (4 float4 per buffer each for A and B)
    const int ldr0 = tid >> 2;        // rows tid>>2, +32, +64, +96
    const int ldq  = tid & 3;

    float acc[32][4];
    #pragma unroll
    for (int t = 0; t < 32; t++)
        #pragma unroll
        for (int q = 0; q < 4; q++) acc[t][q] = 0.0f;

    // prefetch chunk 0
    #pragma unroll
    for (int u = 0; u < 4; u++) {
        int r = ldr0 + u * 32;
        cp16(&As[0][r * 20 + ldq * 4], Ap + (size_t)r * 512 + ldq * 4);
        cp16(&Bs[0][r * 20 + ldq * 4], Bp + (size_t)r * 512 + ldq * 4);
    }
    asm volatile("cp.async.commit_group;" ::: "memory");

    for (int ch = 0; ch < 32; ch++) {
        asm volatile("cp.async.wait_group 0;" ::: "memory");
        __syncthreads();
        if (ch < 31) {
            int k1 = (ch + 1) * 16;
            int nb = (ch + 1) & 1;
            #pragma unroll
            for (int u = 0; u < 4; u++) {
                int r = ldr0 + u * 32;
                cp16(&As[nb][r * 20 + ldq * 4], Ap + (size_t)r * 512 + k1 + ldq * 4);
                cp16(&Bs[nb][r * 20 + ldq * 4], Bp + (size_t)r * 512 + k1 + ldq * 4);
            }
            asm volatile("cp.async.commit_group;" ::: "memory");
        }
        const float* A = As[ch & 1];
        const float* B = Bs[ch & 1];
        #pragma unroll
        for (int ks = 0; ks < 16; ks += 8) {
            uint32_t a[4][4], b[8][2];
            #pragma unroll
            for (int mt = 0; mt < 4; mt++) {
                int rb = (warp_m * 64 + mt * 16 + lr) * 20 + ks + lc;
                a[mt][0] = __float_as_uint(A[rb]);
                a[mt][1] = __float_as_uint(A[rb + 8 * 20]);
                a[mt][2] = __float_as_uint(A[rb + 4]);
                a[mt][3] = __float_as_uint(A[rb + 8 * 20 + 4]);
            }
            #pragma unroll
            for (int nt = 0; nt < 8; nt++) {
                int rb = (warp_n * 64 + nt * 8 + lr) * 20 + ks + lc;
                b[nt][0] = __float_as_uint(B[rb]);
                b[nt][1] = __float_as_uint(B[rb + 4]);
            }
            #pragma unroll
            for (int mt = 0; mt < 4; mt++)
                #pragma unroll
                for (int nt = 0; nt < 8; nt++)
                    mma_tf32(acc[mt * 8 + nt], a[mt], b[nt]);
        }
    }

    float* Op = g_Ot + (size_t)c * NROWS;
    #pragma unroll
    for (int mt = 0; mt < 4; mt++) {
        #pragma unroll
        for (int nt = 0; nt < 8; nt++) {
            int col = j0 + warp_n * 64 + nt * 8 + lc * 2;
            #pragma unroll
            for (int h = 0; h < 2; h++) {
                int row = i0 + warp_m * 64 + mt * 16 + lr + h * 8;
                float2 v;
                v.x = acc[mt * 8 + nt][h * 2 + 0];
                v.y = acc[mt * 8 + nt][h * 2 + 1];
                *(float2*)(Op + (size_t)row * 512 + col) = v;
            }
        }
    }
}

// ---------------- fused: load Ot tile (c-major) + LayerNorm + GEMM(w_out) + gate ----------------
__global__ void __launch_bounds__(256) gemm_out_fused(
    const float* __restrict__ W,
    const float* __restrict__ B,
    const float* __restrict__ fsc,
    const float* __restrict__ fbi,
    const float* __restrict__ gate,
    float* __restrict__ out)
{
    extern __shared__ float dsm[];
    float* tileA = dsm;                    // 128 c x 129
    float* Xs    = dsm + 128 * 129;        // 128 x 20
    float* Ws    = Xs + 128 * 20;          // 16 x 136
    float* s_mu  = Ws + 16 * 136;          // 128
    float* s_rs  = s_mu + 128;             // 128

    const int n0   = blockIdx.x * 128;
    const int tid  = threadIdx.x;
    const int wid  = tid >> 5;
    const int lane = tid & 31;
    const int warp_m = wid >> 2;
    const int warp_n = wid & 3;
    const int lr = lane >> 2;
    const int lc = lane & 3;

    #pragma unroll
    for (int u = 0; u < 16; u++) {
        int idx = tid + u * 256;
        int cc = idx >> 5;
        int q  = idx & 31;
        float4 v = *(const float4*)(g_Ot + (size_t)cc * NROWS + n0 + q * 4);
        float* trow = &tileA[cc * 129 + q * 4];
        trow[0] = v.x; trow[1] = v.y; trow[2] = v.z; trow[3] = v.w;
    }
    __syncthreads();

    #pragma unroll
    for (int rr = 0; rr < 16; rr++) {
        int r = wid * 16 + rr;
        float s = 0.0f, sq = 0.0f;
        #pragma unroll
        for (int m = 0; m < 4; m++) {
            float v = tileA[(lane + m * 32) * 129 + r];
            s += v; sq += v * v;
        }
        #pragma unroll
        for (int o = 16; o > 0; o >>= 1) {
            s  += __shfl_xor_sync(0xffffffffu, s,  o);
            sq += __shfl_xor_sync(0xffffffffu, sq, o);
        }
        if (lane == 0) {
            float mean = s * (1.0f / CC);
            s_mu[r] = mean;
            s_rs[r] = rsqrtf(sq * (1.0f / CC) - mean * mean + 1e-5f);
        }
    }
    __syncthreads();

    float acc[16][4];
    #pragma unroll
    for (int t = 0; t < 16; t++)
        #pragma unroll
        for (int q = 0; q < 4; q++) acc[t][q] = 0.0f;

    for (int k0 = 0; k0 < CC; k0 += 16) {
        #pragma unroll
        for (int u = 0; u < 8; u++) {
            int idx = tid + u * 256;
            int kk = idx & 15;
            int r  = idx >> 4;
            float v = (tileA[(k0 + kk) * 129 + r] - s_mu[r]) * s_rs[r]
                      * fsc[k0 + kk] + fbi[k0 + kk];
            Xs[r * 20 + kk] = tf32r(v);
        }
        #pragma unroll
        for (int u = 0; u < 2; u++) {
            int idx = tid + u * 256;
            int k = idx >> 5;
            int q = idx & 31;
            float4 v = *(const float4*)(W + (size_t)(k0 + k) * CC + q * 4);
            v.x = tf32r(v.x); v.y = tf32r(v.y); v.z = tf32r(v.z); v.w = tf32r(v.w);
            *(float4*)(&Ws[k * 136 + q * 4]) = v;
        }
        __syncthreads();
        #pragma unroll
        for (int ks = 0; ks < 16; ks += 8) {
            uint32_t a[4][4], b[4][2];
            #pragma unroll
            for (int mt = 0; mt < 4; mt++) {
                int rb = (warp_m * 64 + mt * 16 + lr) * 20 + ks + lc;
                a[mt][0] = __float_as_uint(Xs[rb]);
                a[mt][1] = __float_as_uint(Xs[rb + 8 * 20]);
                a[mt][2] = __float_as_uint(Xs[rb + 4]);
                a[mt][3] = __float_as_uint(Xs[rb + 8 * 20 + 4]);
            }
            #pragma unroll
            for (int nt = 0; nt < 4; nt++) {
                int nb = warp_n * 32 + nt * 8 + lr;
                b[nt][0] = __float_as_uint(Ws[(ks + lc) * 136 + nb]);
                b[nt][1] = __float_as_uint(Ws[(ks + 4 + lc) * 136 + nb]);
            }
            #pragma unroll
            for (int mt = 0; mt < 4; mt++)
                #pragma unroll
                for (int nt = 0; nt < 4; nt++)
                    mma_tf32(acc[mt * 4 + nt], a[mt], b[nt]);
        }
        __syncthreads();
    }

    #pragma unroll
    for (int mt = 0; mt < 4; mt++) {
        #pragma unroll
        for (int nt = 0; nt < 4; nt++) {
            int col = warp_n * 32 + nt * 8 + lc * 2;
            float2 bb = *(const float2*)(B + col);
            #pragma unroll
            for (int h = 0; h < 2; h++) {
                int row = n0 + warp_m * 64 + mt * 16 + lr + h * 8;
                float2 gv = *(const float2*)(gate + (size_t)row * CC + col);
                float2 v;
                v.x = (acc[mt * 4 + nt][h * 2 + 0] + bb.x) * gv.x;
                v.y = (acc[mt * 4 + nt][h * 2 + 1] + bb.y) * gv.y;
                *(float2*)(out + (size_t)row * CC + col) = v;
            }
        }
    }
}

// ---------------- host launch ----------------
extern "C" void kernel_launch(void* const* d_in, const int* in_sizes, int n_in,
                              void* d_out, int out_size)
{
    const float* act         = (const float*)d_in[0];
    const float* mask        = (const float*)d_in[1];
    const float* norm_scale  = (const float*)d_in[2];
    const float* norm_bias   = (const float*)d_in[3];
    const float* w_left      = (const float*)d_in[4];
    const float* b_left      = (const float*)d_in[5];
    const float* w_right     = (const float*)d_in[6];
    const float* b_right     = (const float*)d_in[7];
    const float* w_lgate     = (const float*)d_in[8];
    const float* b_lgate     = (const float*)d_in[9];
    const float* w_rgate     = (const float*)d_in[10];
    const float* b_rgate     = (const float*)d_in[11];
    const float* fnorm_scale = (const float*)d_in[12];
    const float* fnorm_bias  = (const float*)d_in[13];
    const float* w_out       = (const float*)d_in[14];
    const float* b_out       = (const float*)d_in[15];
    const float* w_fgate     = (const float*)d_in[16];
    const float* b_fgate     = (const float*)d_in[17];

    float *X, *Fg;
    cudaGetSymbolAddress((void**)&X,  g_X);
    cudaGetSymbolAddress((void**)&Fg, g_Fg);

    const int out_smem = (128 * 129 + 128 * 20 + 16 * 136 + 256) * sizeof(float);
    static int attr_set = 0;
    if (!attr_set) {
        cudaFuncSetAttribute(gemm_out_fused,
                             cudaFuncAttributeMaxDynamicSharedMemorySize, out_smem);
        attr_set = 1;
    }

    // 1) x = LN(act)
    ln_kernel<<<NROWS / 8, 256>>>(act, norm_scale, norm_bias, X);

    // 2) fused projections + gates + mask -> Lt, Rt (c-major)
    proj_lr<<<dim3(NROWS / 128, 4), 256>>>(
        X, w_left, w_lgate, b_left, b_lgate,
        w_right, w_rgate, b_right, b_rgate, mask);

    // 3) final-gate projection: Fg = sigmoid(X @ w_fgate + b_fgate)
    gemm_mma_s<<<NROWS / 128, 256>>>(X, w_fgate, b_fgate, Fg);

    // 4) einsum on tensor cores (cp.async double-buffered) -> Ot (c-major)
    einsum_mma<<<dim3(4, 4, CC), 128>>>();

    // 5+6) fused: LN(Ot) transpose + output projection + final gate
    gemm_out_fused<<<NROWS / 128, 256, out_smem>>>(
        w_out, b_out, fnorm_scale, fnorm_bias, Fg, (float*)d_out);
}

// round 10
// speedup vs baseline: 1.1510x; 1.0196x over previous
#include <cuda_runtime.h>
#include <cstdint>
#include <math.h>

#define LL 512
#define CC 128
#define NROWS (LL*LL)   // 262144

// ---- scratch ----
__device__ float g_X[NROWS*CC];     // normalized input (n-major)
__device__ float g_Lt[CC*NROWS];    // left  gated+masked, c-major planes, k-interleaved [0,4,1,5,2,6,3,7]/8-group
__device__ float g_Rt[CC*NROWS];    // right gated+masked, same layout
__device__ float g_Fg[NROWS*CC];    // sigmoid(final gate), n-major
__device__ float g_Ot[CC*NROWS];    // einsum output, c-major planes [c][i*512+j]

__device__ __forceinline__ float sigf(float x) {
    return 1.0f / (1.0f + __expf(-x));
}
__device__ __forceinline__ float tf32r(float x) {
    uint32_t y;
    asm("cvt.rna.tf32.f32 %0, %1;" : "=r"(y) : "f"(x));
    return __uint_as_float(y);
}
__device__ __forceinline__ void mma_tf32(float* c, const uint32_t* a, const uint32_t* b) {
    asm volatile(
        "mma.sync.aligned.m16n8k8.row.col.f32.tf32.tf32.f32 "
        "{%0,%1,%2,%3}, {%4,%5,%6,%7}, {%8,%9}, {%0,%1,%2,%3};"
        : "+f"(c[0]), "+f"(c[1]), "+f"(c[2]), "+f"(c[3])
        : "r"(a[0]), "r"(a[1]), "r"(a[2]), "r"(a[3]), "r"(b[0]), "r"(b[1]));
}
__device__ __forceinline__ void cp16(float* smem, const float* gmem) {
    uint32_t s = (uint32_t)__cvta_generic_to_shared(smem);
    asm volatile("cp.async.ca.shared.global [%0], [%1], 16;" :: "r"(s), "l"(gmem));
}

// ---------------- LayerNorm: one warp per row of 128 ----------------
__global__ void ln_kernel(const float* __restrict__ in,
                          const float* __restrict__ scale,
                          const float* __restrict__ bias,
                          float* __restrict__ out)
{
    int warp = (blockIdx.x * blockDim.x + threadIdx.x) >> 5;
    int lane = threadIdx.x & 31;
    if (warp >= NROWS) return;
    const float4 v = *(const float4*)(in + (size_t)warp * CC + lane * 4);
    float s  = v.x + v.y + v.z + v.w;
    float sq = v.x*v.x + v.y*v.y + v.z*v.z + v.w*v.w;
    #pragma unroll
    for (int o = 16; o > 0; o >>= 1) {
        s  += __shfl_xor_sync(0xffffffffu, s,  o);
        sq += __shfl_xor_sync(0xffffffffu, sq, o);
    }
    float mean = s * (1.0f / CC);
    float var  = sq * (1.0f / CC) - mean * mean;
    float rstd = rsqrtf(var + 1e-5f);
    float4 sc = *(const float4*)(scale + lane * 4);
    float4 bi = *(const float4*)(bias  + lane * 4);
    float4 r;
    r.x = (v.x - mean) * rstd * sc.x + bi.x;
    r.y = (v.y - mean) * rstd * sc.y + bi.y;
    r.z = (v.z - mean) * rstd * sc.z + bi.z;
    r.w = (v.w - mean) * rstd * sc.w + bi.w;
    *(float4*)(out + (size_t)warp * CC + lane * 4) = r;
}

// ---------------- single-weight tf32 GEMM (Fg): out = sigmoid(X@W + b) ----------------
__global__ void __launch_bounds__(256) gemm_mma_s(
    const float* __restrict__ X,
    const float* __restrict__ W,
    const float* __restrict__ B,
    float* __restrict__ out)
{
    __shared__ __align__(16) float Xs[128 * 20];
    __shared__ __align__(16) float Ws[16 * 136];
    const int r0   = blockIdx.x * 128;
    const int tid  = threadIdx.x;
    const int wid  = tid >> 5;
    const int lane = tid & 31;
    const int warp_m = wid >> 2;
    const int warp_n = wid & 3;
    const int lr = lane >> 2;
    const int lc = lane & 3;

    float acc[16][4];
    #pragma unroll
    for (int t = 0; t < 16; t++)
        #pragma unroll
        for (int q = 0; q < 4; q++) acc[t][q] = 0.0f;

    for (int k0 = 0; k0 < CC; k0 += 16) {
        #pragma unroll
        for (int u = 0; u < 2; u++) {
            int idx = tid + u * 256;
            int r = idx >> 2;
            int q = idx & 3;
            float4 v = *(const float4*)(X + (size_t)(r0 + r) * CC + k0 + q * 4);
            v.x = tf32r(v.x); v.y = tf32r(v.y); v.z = tf32r(v.z); v.w = tf32r(v.w);
            *(float4*)(&Xs[r * 20 + q * 4]) = v;
        }
        #pragma unroll
        for (int u = 0; u < 2; u++) {
            int idx = tid + u * 256;
            int k = idx >> 5;
            int q = idx & 31;
            float4 v = *(const float4*)(W + (size_t)(k0 + k) * CC + q * 4);
            v.x = tf32r(v.x); v.y = tf32r(v.y); v.z = tf32r(v.z); v.w = tf32r(v.w);
            *(float4*)(&Ws[k * 136 + q * 4]) = v;
        }
        __syncthreads();
        #pragma unroll
        for (int ks = 0; ks < 16; ks += 8) {
            uint32_t a[4][4], b[4][2];
            #pragma unroll
            for (int mt = 0; mt < 4; mt++) {
                int rb = (warp_m * 64 + mt * 16 + lr) * 20 + ks + lc;
                a[mt][0] = __float_as_uint(Xs[rb]);
                a[mt][1] = __float_as_uint(Xs[rb + 8 * 20]);
                a[mt][2] = __float_as_uint(Xs[rb + 4]);
                a[mt][3] = __float_as_uint(Xs[rb + 8 * 20 + 4]);
            }
            #pragma unroll
            for (int nt = 0; nt < 4; nt++) {
                int nb = warp_n * 32 + nt * 8 + lr;
                b[nt][0] = __float_as_uint(Ws[(ks + lc) * 136 + nb]);
                b[nt][1] = __float_as_uint(Ws[(ks + 4 + lc) * 136 + nb]);
            }
            #pragma unroll
            for (int mt = 0; mt < 4; mt++)
                #pragma unroll
                for (int nt = 0; nt < 4; nt++)
                    mma_tf32(acc[mt * 4 + nt], a[mt], b[nt]);
        }
        __syncthreads();
    }

    #pragma unroll
    for (int mt = 0; mt < 4; mt++) {
        #pragma unroll
        for (int nt = 0; nt < 4; nt++) {
            int col = warp_n * 32 + nt * 8 + lc * 2;
            float2 bb = *(const float2*)(B + col);
            #pragma unroll
            for (int h = 0; h < 2; h++) {
                int row = r0 + warp_m * 64 + mt * 16 + lr + h * 8;
                float2 v;
                v.x = sigf(acc[mt * 4 + nt][h * 2 + 0] + bb.x);
                v.y = sigf(acc[mt * 4 + nt][h * 2 + 1] + bb.y);
                *(float2*)(out + (size_t)row * CC + col) = v;
            }
        }
    }
}

// ---------------- fused projection + gate + mask + c-major transpose (k-interleaved) ----------------
// grid = (4, 2048): blockIdx.x = (sel<<1)|half  (fast dim -> the 4 variants of one X tile run
// concurrently and share the X tile via L2); blockIdx.y = n-tile.
__global__ void __launch_bounds__(256) proj_lr(
    const float* __restrict__ X,
    const float* __restrict__ w_l,  const float* __restrict__ w_lg,
    const float* __restrict__ b_l,  const float* __restrict__ b_lg,
    const float* __restrict__ w_r,  const float* __restrict__ w_rg,
    const float* __restrict__ b_r,  const float* __restrict__ b_rg,
    const float* __restrict__ mask)
{
    __shared__ __align__(16) float sbuf[128 * 68];
    float* Xs  = sbuf;                 // 128*20
    float* Ws  = sbuf + 2560;          // 16*72
    float* Wgs = sbuf + 2560 + 1152;   // 16*72

    const int sel  = blockIdx.x >> 1;
    const int half = blockIdx.x & 1;
    const float* W  = (sel ? w_r  : w_l)  + half * 64;
    const float* Wg = (sel ? w_rg : w_lg) + half * 64;
    const float* B  = (sel ? b_r  : b_l)  + half * 64;
    const float* Bg = (sel ? b_rg : b_lg) + half * 64;
    float* dstT = (sel ? g_Rt : g_Lt) + (size_t)(half * 64) * NROWS;

    const int n0   = blockIdx.y * 128;
    const int tid  = threadIdx.x;
    const int wid  = tid >> 5;
    const int lane = tid & 31;
    const int warp_m = wid >> 2;
    const int warp_n = wid & 3;
    const int lr = lane >> 2;
    const int lc = lane & 3;

    float acc[8][4], accg[8][4];
    #pragma unroll
    for (int t = 0; t < 8; t++)
        #pragma unroll
        for (int q = 0; q < 4; q++) { acc[t][q] = 0.0f; accg[t][q] = 0.0f; }

    for (int k0 = 0; k0 < CC; k0 += 16) {
        #pragma unroll
        for (int u = 0; u < 2; u++) {
            int idx = tid + u * 256;
            int r = idx >> 2;
            int q = idx & 3;
            float4 v = *(const float4*)(X + (size_t)(n0 + r) * CC + k0 + q * 4);
            v.x = tf32r(v.x); v.y = tf32r(v.y); v.z = tf32r(v.z); v.w = tf32r(v.w);
            *(float4*)(&Xs[r * 20 + q * 4]) = v;
        }
        {
            int k = tid >> 4;
            int q = tid & 15;
            float4 v = *(const float4*)(W + (size_t)(k0 + k) * CC + q * 4);
            v.x = tf32r(v.x); v.y = tf32r(v.y); v.z = tf32r(v.z); v.w = tf32r(v.w);
            *(float4*)(&Ws[k * 72 + q * 4]) = v;
            float4 g = *(const float4*)(Wg + (size_t)(k0 + k) * CC + q * 4);
            g.x = tf32r(g.x); g.y = tf32r(g.y); g.z = tf32r(g.z); g.w = tf32r(g.w);
            *(float4*)(&Wgs[k * 72 + q * 4]) = g;
        }
        __syncthreads();
        #pragma unroll
        for (int ks = 0; ks < 16; ks += 8) {
            uint32_t a[4][4], b[2][2], bg[2][2];
            #pragma unroll
            for (int mt = 0; mt < 4; mt++) {
                int rb = (warp_m * 64 + mt * 16 + lr) * 20 + ks + lc;
                a[mt][0] = __float_as_uint(Xs[rb]);
                a[mt][1] = __float_as_uint(Xs[rb + 8 * 20]);
                a[mt][2] = __float_as_uint(Xs[rb + 4]);
                a[mt][3] = __float_as_uint(Xs[rb + 8 * 20 + 4]);
            }
            #pragma unroll
            for (int nt = 0; nt < 2; nt++) {
                int nb = warp_n * 16 + nt * 8 + lr;
                b[nt][0]  = __float_as_uint(Ws[(ks + lc) * 72 + nb]);
                b[nt][1]  = __float_as_uint(Ws[(ks + 4 + lc) * 72 + nb]);
                bg[nt][0] = __float_as_uint(Wgs[(ks + lc) * 72 + nb]);
                bg[nt][1] = __float_as_uint(Wgs[(ks + 4 + lc) * 72 + nb]);
            }
            #pragma unroll
            for (int mt = 0; mt < 4; mt++)
                #pragma unroll
                for (int nt = 0; nt < 2; nt++) {
                    mma_tf32(acc[mt * 2 + nt], a[mt], b[nt]);
                    mma_tf32(accg[mt * 2 + nt], a[mt], bg[nt]);
                }
        }
        __syncthreads();
    }

    // epilogue: gate+mask into 128x64 smem tile, then transposed c-major write (k-interleaved)
    float (*tile)[68] = (float (*)[68])sbuf;
    #pragma unroll
    for (int mt = 0; mt < 4; mt++) {
        #pragma unroll
        for (int nt = 0; nt < 2; nt++) {
            int col = warp_n * 16 + nt * 8 + lc * 2;
            float2 bb  = *(const float2*)(B + col);
            float2 bbg = *(const float2*)(Bg + col);
            #pragma unroll
            for (int h = 0; h < 2; h++) {
                int rl = warp_m * 64 + mt * 16 + lr + h * 8;
                int n = n0 + rl;
                float pm = mask[n >> 9] * mask[n & 511];
                float vx = (acc[mt * 2 + nt][h * 2 + 0] + bb.x) * pm
                         * sigf(accg[mt * 2 + nt][h * 2 + 0] + bbg.x);
                float vy = (acc[mt * 2 + nt][h * 2 + 1] + bb.y) * pm
                         * sigf(accg[mt * 2 + nt][h * 2 + 1] + bbg.y);
                tile[rl][col]     = tf32r(vx);
                tile[rl][col + 1] = tf32r(vy);
            }
        }
    }
    __syncthreads();
    {
        // interleave order within each 8-k group: position m <- orig O8[m]
        const int O8[8] = {0, 4, 1, 5, 2, 6, 3, 7};
        int c = tid >> 2;
        int h = tid & 3;
        float* dst = dstT + (size_t)c * NROWS + n0 + h * 32;
        #pragma unroll
        for (int q = 0; q < 8; q++) {
            int g8 = (q >> 1) * 8;
            int e  = (q & 1) * 4;
            float4 v;
            v.x = tile[h * 32 + g8 + O8[e + 0]][c];
            v.y = tile[h * 32 + g8 + O8[e + 1]][c];
            v.z = tile[h * 32 + g8 + O8[e + 2]][c];
            v.w = tile[h * 32 + g8 + O8[e + 3]][c];
            *(float4*)(dst + q * 4) = v;
        }
    }
}

// ---------------- einsum: cp.async double-buffered + k-interleaved LDS.64 fragments ----------------
// Block 128i x 128j, 4 warps (2x2), warp tile 64x64, k-chunk 16, stride-24 smem.
// __launch_bounds__(128, 3) pins regs <= 170 so 3 blocks/SM survive.
__global__ void __launch_bounds__(128, 3) einsum_mma()
{
    __shared__ __align__(16) float As[2][128 * 24];
    __shared__ __align__(16) float Bs[2][128 * 24];
    const int c  = blockIdx.z;
    const int i0 = blockIdx.x * 128;
    const int j0 = blockIdx.y * 128;
    const int tid  = threadIdx.x;
    const int wid  = tid >> 5;
    const int lane = tid & 31;
    const int warp_m = wid >> 1;
    const int warp_n = wid & 1;
    const int lr = lane >> 2;
    const int lc = lane & 3;

    const float* Ap = g_Lt + (size_t)c * NROWS + (size_t)i0 * 512;
    const float* Bp = g_Rt + (size_t)c * NROWS + (size_t)j0 * 512;

    const int ldr0 = tid >> 2;
    const int ldq  = tid & 3;

    float acc[32][4];
    #pragma unroll
    for (int t = 0; t < 32; t++)
        #pragma unroll
        for (int q = 0; q < 4; q++) acc[t][q] = 0.0f;

    // prefetch chunk 0
    #pragma unroll
    for (int u = 0; u < 4; u++) {
        int r = ldr0 + u * 32;
        cp16(&As[0][r * 24 + ldq * 4], Ap + (size_t)r * 512 + ldq * 4);
        cp16(&Bs[0][r * 24 + ldq * 4], Bp + (size_t)r * 512 + ldq * 4);
    }
    asm volatile("cp.async.commit_group;" ::: "memory");

    for (int ch = 0; ch < 32; ch++) {
        asm volatile("cp.async.wait_group 0;" ::: "memory");
        __syncthreads();
        if (ch < 31) {
            int k1 = (ch + 1) * 16;
            int nb = (ch + 1) & 1;
            #pragma unroll
            for (int u = 0; u < 4; u++) {
                int r = ldr0 + u * 32;
                cp16(&As[nb][r * 24 + ldq * 4], Ap + (size_t)r * 512 + k1 + ldq * 4);
                cp16(&Bs[nb][r * 24 + ldq * 4], Bp + (size_t)r * 512 + k1 + ldq * 4);
            }
            asm volatile("cp.async.commit_group;" ::: "memory");
        }
        const float* A = As[ch & 1];
        const float* B = Bs[ch & 1];
        #pragma unroll
        for (int ks = 0; ks < 16; ks += 8) {
            uint32_t a[4][4], b[8][2];
            #pragma unroll
            for (int mt = 0; mt < 4; mt++) {
                int rb = (warp_m * 64 + mt * 16 + lr) * 24 + ks + 2 * lc;
                float2 p0 = *(const float2*)(&A[rb]);
                float2 p1 = *(const float2*)(&A[rb + 8 * 24]);
                a[mt][0] = __float_as_uint(p0.x);
                a[mt][1] = __float_as_uint(p1.x);
                a[mt][2] = __float_as_uint(p0.y);
                a[mt][3] = __float_as_uint(p1.y);
            }
            #pragma unroll
            for (int nt = 0; nt < 8; nt++) {
                int rb = (warp_n * 64 + nt * 8 + lr) * 24 + ks + 2 * lc;
                float2 pb = *(const float2*)(&B[rb]);
                b[nt][0] = __float_as_uint(pb.x);
                b[nt][1] = __float_as_uint(pb.y);
            }
            #pragma unroll
            for (int mt = 0; mt < 4; mt++)
                #pragma unroll
                for (int nt = 0; nt < 8; nt++)
                    mma_tf32(acc[mt * 8 + nt], a[mt], b[nt]);
        }
    }

    float* Op = g_Ot + (size_t)c * NROWS;
    #pragma unroll
    for (int mt = 0; mt < 4; mt++) {
        #pragma unroll
        for (int nt = 0; nt < 8; nt++) {
            int col = j0 + warp_n * 64 + nt * 8 + lc * 2;
            #pragma unroll
            for (int h = 0; h < 2; h++) {
                int row = i0 + warp_m * 64 + mt * 16 + lr + h * 8;
                float2 v;
                v.x = acc[mt * 8 + nt][h * 2 + 0];
                v.y = acc[mt * 8 + nt][h * 2 + 1];
                *(float2*)(Op + (size_t)row * 512 + col) = v;
            }
        }
    }
}

// ---------------- fused: load Ot tile (c-major) + LayerNorm + GEMM(w_out) + gate ----------------
__global__ void __launch_bounds__(256) gemm_out_fused(
    const float* __restrict__ W,
    const float* __restrict__ B,
    const float* __restrict__ fsc,
    const float* __restrict__ fbi,
    const float* __restrict__ gate,
    float* __restrict__ out)
{
    extern __shared__ float dsm[];
    float* tileA = dsm;                    // 128 c x 129
    float* Xs    = dsm + 128 * 129;        // 128 x 20
    float* Ws    = Xs + 128 * 20;          // 16 x 136
    float* s_mu  = Ws + 16 * 136;          // 128
    float* s_rs  = s_mu + 128;             // 128

    const int n0   = blockIdx.x * 128;
    const int tid  = threadIdx.x;
    const int wid  = tid >> 5;
    const int lane = tid & 31;
    const int warp_m = wid >> 2;
    const int warp_n = wid & 3;
    const int lr = lane >> 2;
    const int lc = lane & 3;

    #pragma unroll
    for (int u = 0; u < 16; u++) {
        int idx = tid + u * 256;
        int cc = idx >> 5;
        int q  = idx & 31;
        float4 v = *(const float4*)(g_Ot + (size_t)cc * NROWS + n0 + q * 4);
        float* trow = &tileA[cc * 129 + q * 4];
        trow[0] = v.x; trow[1] = v.y; trow[2] = v.z; trow[3] = v.w;
    }
    __syncthreads();

    #pragma unroll
    for (int rr = 0; rr < 16; rr++) {
        int r = wid * 16 + rr;
        float s = 0.0f, sq = 0.0f;
        #pragma unroll
        for (int m = 0; m < 4; m++) {
            float v = tileA[(lane + m * 32) * 129 + r];
            s += v; sq += v * v;
        }
        #pragma unroll
        for (int o = 16; o > 0; o >>= 1) {
            s  += __shfl_xor_sync(0xffffffffu, s,  o);
            sq += __shfl_xor_sync(0xffffffffu, sq, o);
        }
        if (lane == 0) {
            float mean = s * (1.0f / CC);
            s_mu[r] = mean;
            s_rs[r] = rsqrtf(sq * (1.0f / CC) - mean * mean + 1e-5f);
        }
    }
    __syncthreads();

    float acc[16][4];
    #pragma unroll
    for (int t = 0; t < 16; t++)
        #pragma unroll
        for (int q = 0; q < 4; q++) acc[t][q] = 0.0f;

    for (int k0 = 0; k0 < CC; k0 += 16) {
        #pragma unroll
        for (int u = 0; u < 8; u++) {
            int idx = tid + u * 256;
            int kk = idx & 15;
            int r  = idx >> 4;
            float v = (tileA[(k0 + kk) * 129 + r] - s_mu[r]) * s_rs[r]
                      * fsc[k0 + kk] + fbi[k0 + kk];
            Xs[r * 20 + kk] = tf32r(v);
        }
        #pragma unroll
        for (int u = 0; u < 2; u++) {
            int idx = tid + u * 256;
            int k = idx >> 5;
            int q = idx & 31;
            float4 v = *(const float4*)(W + (size_t)(k0 + k) * CC + q * 4);
            v.x = tf32r(v.x); v.y = tf32r(v.y); v.z = tf32r(v.z); v.w = tf32r(v.w);
            *(float4*)(&Ws[k * 136 + q * 4]) = v;
        }
        __syncthreads();
        #pragma unroll
        for (int ks = 0; ks < 16; ks += 8) {
            uint32_t a[4][4], b[4][2];
            #pragma unroll
            for (int mt = 0; mt < 4; mt++) {
                int rb = (warp_m * 64 + mt * 16 + lr) * 20 + ks + lc;
                a[mt][0] = __float_as_uint(Xs[rb]);
                a[mt][1] = __float_as_uint(Xs[rb + 8 * 20]);
                a[mt][2] = __float_as_uint(Xs[rb + 4]);
                a[mt][3] = __float_as_uint(Xs[rb + 8 * 20 + 4]);
            }
            #pragma unroll
            for (int nt = 0; nt < 4; nt++) {
                int nb = warp_n * 32 + nt * 8 + lr;
                b[nt][0] = __float_as_uint(Ws[(ks + lc) * 136 + nb]);
                b[nt][1] = __float_as_uint(Ws[(ks + 4 + lc) * 136 + nb]);
            }
            #pragma unroll
            for (int mt = 0; mt < 4; mt++)
                #pragma unroll
                for (int nt = 0; nt < 4; nt++)
                    mma_tf32(acc[mt * 4 + nt], a[mt], b[nt]);
        }
        __syncthreads();
    }

    #pragma unroll
    for (int mt = 0; mt < 4; mt++) {
        #pragma unroll
        for (int nt = 0; nt < 4; nt++) {
            int col = warp_n * 32 + nt * 8 + lc * 2;
            float2 bb = *(const float2*)(B + col);
            #pragma unroll
            for (int h = 0; h < 2; h++) {
                int row = n0 + warp_m * 64 + mt * 16 + lr + h * 8;
                float2 gv = *(const float2*)(gate + (size_t)row * CC + col);
                float2 v;
                v.x = (acc[mt * 4 + nt][h * 2 + 0] + bb.x) * gv.x;
                v.y = (acc[mt * 4 + nt][h * 2 + 1] + bb.y) * gv.y;
                *(float2*)(out + (size_t)row * CC + col) = v;
            }
        }
    }
}

// ---------------- host launch ----------------
extern "C" void kernel_launch(void* const* d_in, const int* in_sizes, int n_in,
                              void* d_out, int out_size)
{
    const float* act         = (const float*)d_in[0];
    const float* mask        = (const float*)d_in[1];
    const float* norm_scale  = (const float*)d_in[2];
    const float* norm_bias   = (const float*)d_in[3];
    const float* w_left      = (const float*)d_in[4];
    const float* b_left      = (const float*)d_in[5];
    const float* w_right     = (const float*)d_in[6];
    const float* b_right     = (const float*)d_in[7];
    const float* w_lgate     = (const float*)d_in[8];
    const float* b_lgate     = (const float*)d_in[9];
    const float* w_rgate     = (const float*)d_in[10];
    const float* b_rgate     = (const float*)d_in[11];
    const float* fnorm_scale = (const float*)d_in[12];
    const float* fnorm_bias  = (const float*)d_in[13];
    const float* w_out       = (const float*)d_in[14];
    const float* b_out       = (const float*)d_in[15];
    const float* w_fgate     = (const float*)d_in[16];
    const float* b_fgate     = (const float*)d_in[17];

    float *X, *Fg;
    cudaGetSymbolAddress((void**)&X,  g_X);
    cudaGetSymbolAddress((void**)&Fg, g_Fg);

    const int out_smem = (128 * 129 + 128 * 20 + 16 * 136 + 256) * sizeof(float);
    static int attr_set = 0;
    if (!attr_set) {
        cudaFuncSetAttribute(gemm_out_fused,
                             cudaFuncAttributeMaxDynamicSharedMemorySize, out_smem);
        attr_set = 1;
    }

    // 1) x = LN(act)
    ln_kernel<<<NROWS / 8, 256>>>(act, norm_scale, norm_bias, X);

    // 2) fused projections + gates + mask -> Lt, Rt (c-major, k-interleaved)
    //    (4 variants fast in grid -> X tile L2 reuse)
    proj_lr<<<dim3(4, NROWS / 128), 256>>>(
        X, w_left, w_lgate, b_left, b_lgate,
        w_right, w_rgate, b_right, b_rgate, mask);

    // 3) final-gate projection: Fg = sigmoid(X @ w_fgate + b_fgate)
    gemm_mma_s<<<NROWS / 128, 256>>>(X, w_fgate, b_fgate, Fg);

    // 4) einsum on tensor cores (cp.async pipelined, LDS.64 fragments) -> Ot (c-major)
    einsum_mma<<<dim3(4, 4, CC), 128>>>();

    // 5+6) fused: LN(Ot) transpose + output projection + final gate
    gemm_out_fused<<<NROWS / 128, 256, out_smem>>>(
        w_out, b_out, fnorm_scale, fnorm_bias, Fg, (float*)d_out);
}

// round 11
// speedup vs baseline: 1.2153x; 1.0559x over previous
#include <cuda_runtime.h>
#include <cstdint>
#include <math.h>

#define LL 512
#define CC 128
#define NROWS (LL*LL)   // 262144

// ---- scratch ----
__device__ float g_X[NROWS*CC];     // normalized input, tf32-rounded (n-major)
__device__ float g_Wt[6*CC*CC];     // tf32-rounded weights: w_l, w_lg, w_r, w_rg, w_fgate, w_out
__device__ float g_Lt[CC*NROWS];    // left  gated+masked, c-major planes, k-interleaved [0,4,1,5,2,6,3,7]/8-group
__device__ float g_Rt[CC*NROWS];    // right gated+masked, same layout
__device__ float g_Fg[NROWS*CC];    // sigmoid(final gate), n-major
__device__ float g_Ot[CC*NROWS];    // einsum output, c-major planes [c][i*512+j]

__device__ __forceinline__ float sigf(float x) {
    return 1.0f / (1.0f + __expf(-x));
}
__device__ __forceinline__ float tf32r(float x) {
    uint32_t y;
    asm("cvt.rna.tf32.f32 %0, %1;" : "=r"(y) : "f"(x));
    return __uint_as_float(y);
}
__device__ __forceinline__ void mma_tf32(float* c, const uint32_t* a, const uint32_t* b) {
    asm volatile(
        "mma.sync.aligned.m16n8k8.row.col.f32.tf32.tf32.f32 "
        "{%0,%1,%2,%3}, {%4,%5,%6,%7}, {%8,%9}, {%0,%1,%2,%3};"
        : "+f"(c[0]), "+f"(c[1]), "+f"(c[2]), "+f"(c[3])
        : "r"(a[0]), "r"(a[1]), "r"(a[2]), "r"(a[3]), "r"(b[0]), "r"(b[1]));
}
__device__ __forceinline__ void cp16(float* smem, const float* gmem) {
    uint32_t s = (uint32_t)__cvta_generic_to_shared(smem);
    asm volatile("cp.async.ca.shared.global [%0], [%1], 16;" :: "r"(s), "l"(gmem));
}

// ---------------- weight prep: tf32-round all 6 weights once ----------------
__global__ void prep_weights(const float* __restrict__ w0, const float* __restrict__ w1,
                             const float* __restrict__ w2, const float* __restrict__ w3,
                             const float* __restrict__ w4, const float* __restrict__ w5)
{
    int i = blockIdx.x * 256 + threadIdx.x;       // 0 .. 98303
    int w = i >> 14;
    int e = i & 16383;
    const float* src = (w == 0) ? w0 : (w == 1) ? w1 : (w == 2) ? w2
                     : (w == 3) ? w3 : (w == 4) ? w4 : w5;
    g_Wt[i] = tf32r(src[e]);
}

// ---------------- LayerNorm: one warp per row of 128; writes tf32-rounded ----------------
__global__ void ln_kernel(const float* __restrict__ in,
                          const float* __restrict__ scale,
                          const float* __restrict__ bias,
                          float* __restrict__ out)
{
    int warp = (blockIdx.x * blockDim.x + threadIdx.x) >> 5;
    int lane = threadIdx.x & 31;
    if (warp >= NROWS) return;
    const float4 v = *(const float4*)(in + (size_t)warp * CC + lane * 4);
    float s  = v.x + v.y + v.z + v.w;
    float sq = v.x*v.x + v.y*v.y + v.z*v.z + v.w*v.w;
    #pragma unroll
    for (int o = 16; o > 0; o >>= 1) {
        s  += __shfl_xor_sync(0xffffffffu, s,  o);
        sq += __shfl_xor_sync(0xffffffffu, sq, o);
    }
    float mean = s * (1.0f / CC);
    float var  = sq * (1.0f / CC) - mean * mean;
    float rstd = rsqrtf(var + 1e-5f);
    float4 sc = *(const float4*)(scale + lane * 4);
    float4 bi = *(const float4*)(bias  + lane * 4);
    float4 r;
    r.x = tf32r((v.x - mean) * rstd * sc.x + bi.x);
    r.y = tf32r((v.y - mean) * rstd * sc.y + bi.y);
    r.z = tf32r((v.z - mean) * rstd * sc.z + bi.z);
    r.w = tf32r((v.w - mean) * rstd * sc.w + bi.w);
    *(float4*)(out + (size_t)warp * CC + lane * 4) = r;
}

// ---------------- Fg GEMM (cp.async pipelined): out = sigmoid(X@W + b) ----------------
__global__ void __launch_bounds__(256) gemm_mma_s(
    const float* __restrict__ X,
    const float* __restrict__ B,
    float* __restrict__ out)
{
    __shared__ __align__(16) float sbuf[2*2560 + 2*2176];
    float* Xs0 = sbuf;             // [2][128*20]
    float* Ws0 = sbuf + 5120;      // [2][16*136]
    const float* W = g_Wt + 4 * CC * CC;
    const int r0   = blockIdx.x * 128;
    const int tid  = threadIdx.x;
    const int wid  = tid >> 5;
    const int lane = tid & 31;
    const int warp_m = wid >> 2;
    const int warp_n = wid & 3;
    const int lr = lane >> 2;
    const int lc = lane & 3;

    float acc[16][4];
    #pragma unroll
    for (int t = 0; t < 16; t++)
        #pragma unroll
        for (int q = 0; q < 4; q++) acc[t][q] = 0.0f;

    // prefetch chunk 0
    {
        #pragma unroll
        for (int u = 0; u < 2; u++) {
            int idx = tid + u * 256;
            int r = idx >> 2, q = idx & 3;
            cp16(&Xs0[r * 20 + q * 4], X + (size_t)(r0 + r) * CC + q * 4);
        }
        #pragma unroll
        for (int u = 0; u < 2; u++) {
            int idx = tid + u * 256;
            int k = idx >> 5, q = idx & 31;
            cp16(&Ws0[k * 136 + q * 4], W + (size_t)k * CC + q * 4);
        }
        asm volatile("cp.async.commit_group;" ::: "memory");
    }

    for (int ch = 0; ch < 8; ch++) {
        asm volatile("cp.async.wait_group 0;" ::: "memory");
        __syncthreads();
        if (ch < 7) {
            int k0 = (ch + 1) * 16;
            int buf = (ch + 1) & 1;
            #pragma unroll
            for (int u = 0; u < 2; u++) {
                int idx = tid + u * 256;
                int r = idx >> 2, q = idx & 3;
                cp16(&Xs0[buf * 2560 + r * 20 + q * 4], X + (size_t)(r0 + r) * CC + k0 + q * 4);
            }
            #pragma unroll
            for (int u = 0; u < 2; u++) {
                int idx = tid + u * 256;
                int k = idx >> 5, q = idx & 31;
                cp16(&Ws0[buf * 2176 + k * 136 + q * 4], W + (size_t)(k0 + k) * CC + q * 4);
            }
            asm volatile("cp.async.commit_group;" ::: "memory");
        }
        const float* Xs = Xs0 + (ch & 1) * 2560;
        const float* Ws = Ws0 + (ch & 1) * 2176;
        #pragma unroll
        for (int ks = 0; ks < 16; ks += 8) {
            uint32_t a[4][4], b[4][2];
            #pragma unroll
            for (int mt = 0; mt < 4; mt++) {
                int rb = (warp_m * 64 + mt * 16 + lr) * 20 + ks + lc;
                a[mt][0] = __float_as_uint(Xs[rb]);
                a[mt][1] = __float_as_uint(Xs[rb + 8 * 20]);
                a[mt][2] = __float_as_uint(Xs[rb + 4]);
                a[mt][3] = __float_as_uint(Xs[rb + 8 * 20 + 4]);
            }
            #pragma unroll
            for (int nt = 0; nt < 4; nt++) {
                int nb = warp_n * 32 + nt * 8 + lr;
                b[nt][0] = __float_as_uint(Ws[(ks + lc) * 136 + nb]);
                b[nt][1] = __float_as_uint(Ws[(ks + 4 + lc) * 136 + nb]);
            }
            #pragma unroll
            for (int mt = 0; mt < 4; mt++)
                #pragma unroll
                for (int nt = 0; nt < 4; nt++)
                    mma_tf32(acc[mt * 4 + nt], a[mt], b[nt]);
        }
    }

    #pragma unroll
    for (int mt = 0; mt < 4; mt++) {
        #pragma unroll
        for (int nt = 0; nt < 4; nt++) {
            int col = warp_n * 32 + nt * 8 + lc * 2;
            float2 bb = *(const float2*)(B + col);
            #pragma unroll
            for (int h = 0; h < 2; h++) {
                int row = r0 + warp_m * 64 + mt * 16 + lr + h * 8;
                float2 v;
                v.x = sigf(acc[mt * 4 + nt][h * 2 + 0] + bb.x);
                v.y = sigf(acc[mt * 4 + nt][h * 2 + 1] + bb.y);
                *(float2*)(out + (size_t)row * CC + col) = v;
            }
        }
    }
}

// ---------------- fused projection + gate + mask + c-major transpose (pipelined) ----------------
// grid = (4, 2048): blockIdx.x = (sel<<1)|half (fast dim -> X tile L2 reuse).
__global__ void __launch_bounds__(256) proj_lr(
    const float* __restrict__ b_l,  const float* __restrict__ b_lg,
    const float* __restrict__ b_r,  const float* __restrict__ b_rg,
    const float* __restrict__ mask)
{
    __shared__ __align__(16) float sbuf[2*2560 + 4*1152];   // 9728 floats; epilogue tile (8704) reuses
    float* Xs0  = sbuf;            // [2][128*20]
    float* Ws0  = sbuf + 5120;     // [2][16*72]
    float* Wgs0 = sbuf + 7424;     // [2][16*72]

    const int sel  = blockIdx.x >> 1;
    const int half = blockIdx.x & 1;
    const float* W  = g_Wt + (sel ? 2 : 0) * CC * CC + half * 64;
    const float* Wg = g_Wt + (sel ? 3 : 1) * CC * CC + half * 64;
    const float* B  = (sel ? b_r  : b_l)  + half * 64;
    const float* Bg = (sel ? b_rg : b_lg) + half * 64;
    float* dstT = (sel ? g_Rt : g_Lt) + (size_t)(half * 64) * NROWS;

    const int n0   = blockIdx.y * 128;
    const int tid  = threadIdx.x;
    const int wid  = tid >> 5;
    const int lane = tid & 31;
    const int warp_m = wid >> 2;
    const int warp_n = wid & 3;
    const int lr = lane >> 2;
    const int lc = lane & 3;

    float acc[8][4], accg[8][4];
    #pragma unroll
    for (int t = 0; t < 8; t++)
        #pragma unroll
        for (int q = 0; q < 4; q++) { acc[t][q] = 0.0f; accg[t][q] = 0.0f; }

    // prefetch chunk 0
    {
        #pragma unroll
        for (int u = 0; u < 2; u++) {
            int idx = tid + u * 256;
            int r = idx >> 2, q = idx & 3;
            cp16(&Xs0[r * 20 + q * 4], g_X + (size_t)(n0 + r) * CC + q * 4);
        }
        int k = tid >> 4, q = tid & 15;
        cp16(&Ws0[k * 72 + q * 4],  W  + (size_t)k * CC + q * 4);
        cp16(&Wgs0[k * 72 + q * 4], Wg + (size_t)k * CC + q * 4);
        asm volatile("cp.async.commit_group;" ::: "memory");
    }

    for (int ch = 0; ch < 8; ch++) {
        asm volatile("cp.async.wait_group 0;" ::: "memory");
        __syncthreads();
        if (ch < 7) {
            int k0 = (ch + 1) * 16;
            int buf = (ch + 1) & 1;
            #pragma unroll
            for (int u = 0; u < 2; u++) {
                int idx = tid + u * 256;
                int r = idx >> 2, q = idx & 3;
                cp16(&Xs0[buf * 2560 + r * 20 + q * 4], g_X + (size_t)(n0 + r) * CC + k0 + q * 4);
            }
            int k = tid >> 4, q = tid & 15;
            cp16(&Ws0[buf * 1152 + k * 72 + q * 4],  W  + (size_t)(k0 + k) * CC + q * 4);
            cp16(&Wgs0[buf * 1152 + k * 72 + q * 4], Wg + (size_t)(k0 + k) * CC + q * 4);
            asm volatile("cp.async.commit_group;" ::: "memory");
        }
        const float* Xs  = Xs0  + (ch & 1) * 2560;
        const float* Ws  = Ws0  + (ch & 1) * 1152;
        const float* Wgs = Wgs0 + (ch & 1) * 1152;
        #pragma unroll
        for (int ks = 0; ks < 16; ks += 8) {
            uint32_t a[4][4], b[2][2], bg[2][2];
            #pragma unroll
            for (int mt = 0; mt < 4; mt++) {
                int rb = (warp_m * 64 + mt * 16 + lr) * 20 + ks + lc;
                a[mt][0] = __float_as_uint(Xs[rb]);
                a[mt][1] = __float_as_uint(Xs[rb + 8 * 20]);
                a[mt][2] = __float_as_uint(Xs[rb + 4]);
                a[mt][3] = __float_as_uint(Xs[rb + 8 * 20 + 4]);
            }
            #pragma unroll
            for (int nt = 0; nt < 2; nt++) {
                int nb = warp_n * 16 + nt * 8 + lr;
                b[nt][0]  = __float_as_uint(Ws[(ks + lc) * 72 + nb]);
                b[nt][1]  = __float_as_uint(Ws[(ks + 4 + lc) * 72 + nb]);
                bg[nt][0] = __float_as_uint(Wgs[(ks + lc) * 72 + nb]);
                bg[nt][1] = __float_as_uint(Wgs[(ks + 4 + lc) * 72 + nb]);
            }
            #pragma unroll
            for (int mt = 0; mt < 4; mt++)
                #pragma unroll
                for (int nt = 0; nt < 2; nt++) {
                    mma_tf32(acc[mt * 2 + nt], a[mt], b[nt]);
                    mma_tf32(accg[mt * 2 + nt], a[mt], bg[nt]);
                }
        }
    }
    __syncthreads();   // last chunk's smem reads done before tile reuse

    // epilogue: gate+mask into 128x64 smem tile, then transposed c-major write (k-interleaved)
    float (*tile)[68] = (float (*)[68])sbuf;
    #pragma unroll
    for (int mt = 0; mt < 4; mt++) {
        #pragma unroll
        for (int nt = 0; nt < 2; nt++) {
            int col = warp_n * 16 + nt * 8 + lc * 2;
            float2 bb  = *(const float2*)(B + col);
            float2 bbg = *(const float2*)(Bg + col);
            #pragma unroll
            for (int h = 0; h < 2; h++) {
                int rl = warp_m * 64 + mt * 16 + lr + h * 8;
                int n = n0 + rl;
                float pm = mask[n >> 9] * mask[n & 511];
                float vx = (acc[mt * 2 + nt][h * 2 + 0] + bb.x) * pm
                         * sigf(accg[mt * 2 + nt][h * 2 + 0] + bbg.x);
                float vy = (acc[mt * 2 + nt][h * 2 + 1] + bb.y) * pm
                         * sigf(accg[mt * 2 + nt][h * 2 + 1] + bbg.y);
                tile[rl][col]     = tf32r(vx);
                tile[rl][col + 1] = tf32r(vy);
            }
        }
    }
    __syncthreads();
    {
        const int O8[8] = {0, 4, 1, 5, 2, 6, 3, 7};
        int c = tid >> 2;
        int h = tid & 3;
        float* dst = dstT + (size_t)c * NROWS + n0 + h * 32;
        #pragma unroll
        for (int q = 0; q < 8; q++) {
            int g8 = (q >> 1) * 8;
            int e  = (q & 1) * 4;
            float4 v;
            v.x = tile[h * 32 + g8 + O8[e + 0]][c];
            v.y = tile[h * 32 + g8 + O8[e + 1]][c];
            v.z = tile[h * 32 + g8 + O8[e + 2]][c];
            v.w = tile[h * 32 + g8 + O8[e + 3]][c];
            *(float4*)(dst + q * 4) = v;
        }
    }
}

// ---------------- einsum: cp.async double-buffered + k-interleaved LDS.64 fragments ----------------
__global__ void __launch_bounds__(128, 3) einsum_mma()
{
    __shared__ __align__(16) float As[2][128 * 24];
    __shared__ __align__(16) float Bs[2][128 * 24];
    const int c  = blockIdx.z;
    const int i0 = blockIdx.x * 128;
    const int j0 = blockIdx.y * 128;
    const int tid  = threadIdx.x;
    const int wid  = tid >> 5;
    const int lane = tid & 31;
    const int warp_m = wid >> 1;
    const int warp_n = wid & 1;
    const int lr = lane >> 2;
    const int lc = lane & 3;

    const float* Ap = g_Lt + (size_t)c * NROWS + (size_t)i0 * 512;
    const float* Bp = g_Rt + (size_t)c * NROWS + (size_t)j0 * 512;

    const int ldr0 = tid >> 2;
    const int ldq  = tid & 3;

    float acc[32][4];
    #pragma unroll
    for (int t = 0; t < 32; t++)
        #pragma unroll
        for (int q = 0; q < 4; q++) acc[t][q] = 0.0f;

    #pragma unroll
    for (int u = 0; u < 4; u++) {
        int r = ldr0 + u * 32;
        cp16(&As[0][r * 24 + ldq * 4], Ap + (size_t)r * 512 + ldq * 4);
        cp16(&Bs[0][r * 24 + ldq * 4], Bp + (size_t)r * 512 + ldq * 4);
    }
    asm volatile("cp.async.commit_group;" ::: "memory");

    for (int ch = 0; ch < 32; ch++) {
        asm volatile("cp.async.wait_group 0;" ::: "memory");
        __syncthreads();
        if (ch < 31) {
            int k1 = (ch + 1) * 16;
            int nb = (ch + 1) & 1;
            #pragma unroll
            for (int u = 0; u < 4; u++) {
                int r = ldr0 + u * 32;
                cp16(&As[nb][r * 24 + ldq * 4], Ap + (size_t)r * 512 + k1 + ldq * 4);
                cp16(&Bs[nb][r * 24 + ldq * 4], Bp + (size_t)r * 512 + k1 + ldq * 4);
            }
            asm volatile("cp.async.commit_group;" ::: "memory");
        }
        const float* A = As[ch & 1];
        const float* B = Bs[ch & 1];
        #pragma unroll
        for (int ks = 0; ks < 16; ks += 8) {
            uint32_t a[4][4], b[8][2];
            #pragma unroll
            for (int mt = 0; mt < 4; mt++) {
                int rb = (warp_m * 64 + mt * 16 + lr) * 24 + ks + 2 * lc;
                float2 p0 = *(const float2*)(&A[rb]);
                float2 p1 = *(const float2*)(&A[rb + 8 * 24]);
                a[mt][0] = __float_as_uint(p0.x);
                a[mt][1] = __float_as_uint(p1.x);
                a[mt][2] = __float_as_uint(p0.y);
                a[mt][3] = __float_as_uint(p1.y);
            }
            #pragma unroll
            for (int nt = 0; nt < 8; nt++) {
                int rb = (warp_n * 64 + nt * 8 + lr) * 24 + ks + 2 * lc;
                float2 pb = *(const float2*)(&B[rb]);
                b[nt][0] = __float_as_uint(pb.x);
                b[nt][1] = __float_as_uint(pb.y);
            }
            #pragma unroll
            for (int mt = 0; mt < 4; mt++)
                #pragma unroll
                for (int nt = 0; nt < 8; nt++)
                    mma_tf32(acc[mt * 8 + nt], a[mt], b[nt]);
        }
    }

    float* Op = g_Ot + (size_t)c * NROWS;
    #pragma unroll
    for (int mt = 0; mt < 4; mt++) {
        #pragma unroll
        for (int nt = 0; nt < 8; nt++) {
            int col = j0 + warp_n * 64 + nt * 8 + lc * 2;
            #pragma unroll
            for (int h = 0; h < 2; h++) {
                int row = i0 + warp_m * 64 + mt * 16 + lr + h * 8;
                float2 v;
                v.x = acc[mt * 8 + nt][h * 2 + 0];
                v.y = acc[mt * 8 + nt][h * 2 + 1];
                *(float2*)(Op + (size_t)row * 512 + col) = v;
            }
        }
    }
}

// ---------------- fused: load Ot tile (c-major) + LayerNorm + GEMM(w_out) + gate ----------------
__global__ void __launch_bounds__(256) gemm_out_fused(
    const float* __restrict__ B,
    const float* __restrict__ fsc,
    const float* __restrict__ fbi,
    const float* __restrict__ gate,
    float* __restrict__ out)
{
    extern __shared__ float dsm[];
    float* tileA = dsm;                    // 128 c x 129
    float* Xs    = dsm + 128 * 129;        // 128 x 20
    float* Ws    = Xs + 128 * 20;          // 16 x 136
    float* s_mu  = Ws + 16 * 136;          // 128
    float* s_rs  = s_mu + 128;             // 128
    const float* W = g_Wt + 5 * CC * CC;   // pre-rounded

    const int n0   = blockIdx.x * 128;
    const int tid  = threadIdx.x;
    const int wid  = tid >> 5;
    const int lane = tid & 31;
    const int warp_m = wid >> 2;
    const int warp_n = wid & 3;
    const int lr = lane >> 2;
    const int lc = lane & 3;

    #pragma unroll
    for (int u = 0; u < 16; u++) {
        int idx = tid + u * 256;
        int cc = idx >> 5;
        int q  = idx & 31;
        float4 v = *(const float4*)(g_Ot + (size_t)cc * NROWS + n0 + q * 4);
        float* trow = &tileA[cc * 129 + q * 4];
        trow[0] = v.x; trow[1] = v.y; trow[2] = v.z; trow[3] = v.w;
    }
    __syncthreads();

    #pragma unroll
    for (int rr = 0; rr < 16; rr++) {
        int r = wid * 16 + rr;
        float s = 0.0f, sq = 0.0f;
        #pragma unroll
        for (int m = 0; m < 4; m++) {
            float v = tileA[(lane + m * 32) * 129 + r];
            s += v; sq += v * v;
        }
        #pragma unroll
        for (int o = 16; o > 0; o >>= 1) {
            s  += __shfl_xor_sync(0xffffffffu, s,  o);
            sq += __shfl_xor_sync(0xffffffffu, sq, o);
        }
        if (lane == 0) {
            float mean = s * (1.0f / CC);
            s_mu[r] = mean;
            s_rs[r] = rsqrtf(sq * (1.0f / CC) - mean * mean + 1e-5f);
        }
    }
    __syncthreads();

    float acc[16][4];
    #pragma unroll
    for (int t = 0; t < 16; t++)
        #pragma unroll
        for (int q = 0; q < 4; q++) acc[t][q] = 0.0f;

    for (int k0 = 0; k0 < CC; k0 += 16) {
        #pragma unroll
        for (int u = 0; u < 8; u++) {
            int idx = tid + u * 256;
            int kk = idx & 15;
            int r  = idx >> 4;
            float v = (tileA[(k0 + kk) * 129 + r] - s_mu[r]) * s_rs[r]
                      * fsc[k0 + kk] + fbi[k0 + kk];
            Xs[r * 20 + kk] = tf32r(v);
        }
        #pragma unroll
        for (int u = 0; u < 2; u++) {
            int idx = tid + u * 256;
            int k = idx >> 5;
            int q = idx & 31;
            *(float4*)(&Ws[k * 136 + q * 4]) = *(const float4*)(W + (size_t)(k0 + k) * CC + q * 4);
        }
        __syncthreads();
        #pragma unroll
        for (int ks = 0; ks < 16; ks += 8) {
            uint32_t a[4][4], b[4][2];
            #pragma unroll
            for (int mt = 0; mt < 4; mt++) {
                int rb = (warp_m * 64 + mt * 16 + lr) * 20 + ks + lc;
                a[mt][0] = __float_as_uint(Xs[rb]);
                a[mt][1] = __float_as_uint(Xs[rb + 8 * 20]);
                a[mt][2] = __float_as_uint(Xs[rb + 4]);
                a[mt][3] = __float_as_uint(Xs[rb + 8 * 20 + 4]);
            }
            #pragma unroll
            for (int nt = 0; nt < 4; nt++) {
                int nb = warp_n * 32 + nt * 8 + lr;
                b[nt][0] = __float_as_uint(Ws[(ks + lc) * 136 + nb]);
                b[nt][1] = __float_as_uint(Ws[(ks + 4 + lc) * 136 + nb]);
            }
            #pragma unroll
            for (int mt = 0; mt < 4; mt++)
                #pragma unroll
                for (int nt = 0; nt < 4; nt++)
                    mma_tf32(acc[mt * 4 + nt], a[mt], b[nt]);
        }
        __syncthreads();
    }

    #pragma unroll
    for (int mt = 0; mt < 4; mt++) {
        #pragma unroll
        for (int nt = 0; nt < 4; nt++) {
            int col = warp_n * 32 + nt * 8 + lc * 2;
            float2 bb = *(const float2*)(B + col);
            #pragma unroll
            for (int h = 0; h < 2; h++) {
                int row = n0 + warp_m * 64 + mt * 16 + lr + h * 8;
                float2 gv = *(const float2*)(gate + (size_t)row * CC + col);
                float2 v;
                v.x = (acc[mt * 4 + nt][h * 2 + 0] + bb.x) * gv.x;
                v.y = (acc[mt * 4 + nt][h * 2 + 1] + bb.y) * gv.y;
                *(float2*)(out + (size_t)row * CC + col) = v;
            }
        }
    }
}

// ---------------- host launch ----------------
extern "C" void kernel_launch(void* const* d_in, const int* in_sizes, int n_in,
                              void* d_out, int out_size)
{
    const float* act         = (const float*)d_in[0];
    const float* mask        = (const float*)d_in[1];
    const float* norm_scale  = (const float*)d_in[2];
    const float* norm_bias   = (const float*)d_in[3];
    const float* w_left      = (const float*)d_in[4];
    const float* b_left      = (const float*)d_in[5];
    const float* w_right     = (const float*)d_in[6];
    const float* b_right     = (const float*)d_in[7];
    const float* w_lgate     = (const float*)d_in[8];
    const float* b_lgate     = (const float*)d_in[9];
    const float* w_rgate     = (const float*)d_in[10];
    const float* b_rgate     = (const float*)d_in[11];
    const float* fnorm_scale = (const float*)d_in[12];
    const float* fnorm_bias  = (const float*)d_in[13];
    const float* w_out       = (const float*)d_in[14];
    const float* b_out       = (const float*)d_in[15];
    const float* w_fgate     = (const float*)d_in[16];
    const float* b_fgate     = (const float*)d_in[17];

    float *X, *Fg;
    cudaGetSymbolAddress((void**)&X,  g_X);
    cudaGetSymbolAddress((void**)&Fg, g_Fg);

    const int out_smem = (128 * 129 + 128 * 20 + 16 * 136 + 256) * sizeof(float);
    static int attr_set = 0;
    if (!attr_set) {
        cudaFuncSetAttribute(gemm_out_fused,
                             cudaFuncAttributeMaxDynamicSharedMemorySize, out_smem);
        attr_set = 1;
    }

    // 0) tf32-round all weights once
    prep_weights<<<(6 * CC * CC) / 256, 256>>>(
        w_left, w_lgate, w_right, w_rgate, w_fgate, w_out);

    // 1) x = LN(act), tf32-rounded
    ln_kernel<<<NROWS / 8, 256>>>(act, norm_scale, norm_bias, X);

    // 2) fused projections + gates + mask -> Lt, Rt (pipelined)
    proj_lr<<<dim3(4, NROWS / 128), 256>>>(
        b_left, b_lgate, b_right, b_rgate, mask);

    // 3) final-gate projection: Fg = sigmoid(X @ w_fgate + b_fgate) (pipelined)
    gemm_mma_s<<<NROWS / 128, 256>>>(X, b_fgate, Fg);

    // 4) einsum on tensor cores -> Ot (c-major)
    einsum_mma<<<dim3(4, 4, CC), 128>>>();

    // 5+6) fused: LN(Ot) transpose + output projection + final gate
    gemm_out_fused<<<NROWS / 128, 256, out_smem>>>(
        b_out, fnorm_scale, fnorm_bias, Fg, (float*)d_out);
}